// round 5
// baseline (speedup 1.0000x reference)
#include <cuda_runtime.h>
#include <math.h>

// E=8 A=128 TGT=3 HID=16 OUT=128 B=64 W=128 F=132
struct Params {
  const float *Local, *Remote;
  const float *gWih0,*gWhh0,*gbih0,*gbhh0,*gWih1,*gWhh1,*gbih1,*gbhh1;
  const float *aew1,*aeb1,*aew2,*aeb2,*aeg,*aebt;
  const float *mdw1,*mdb1,*mdw2,*mdb2,*mdg,*mdbt;
  const float *mWih0,*mWhh0,*mbih0,*mbhh0,*mWih1,*mWhh1,*mbih1,*mbhh1;
  float* out;
};

__device__ __align__(16) float g_G[128*128*8];   // gate GRU hidden (pre-softmax) [seq][t][8]
__device__ __align__(16) float g_P[16384*128];   // expert-1 GEMM result
__device__ __align__(16) float g_H[16384*16];    // mixed hidden (pre-BN)
__device__             float g_stats[64];        // [call*32 + (sum16|sumsq16)]
__device__ __align__(16) float g_XW0[8192*48];   // mixer layer0 input projection (incl. bih0)
__device__ __align__(16) float g_HF[64*16];      // mixer final hidden

#define DEVFN __device__ __forceinline__
DEVFN float sigf(float x){ float e=__expf(-x); return __fdividef(1.f,1.f+e); }
DEVFN float tanhf_(float x){
  x=fminf(fmaxf(x,-15.f),15.f);
  float e=__expf(-2.f*x);
  return (1.f-e)*__fdividef(1.f,1.f+e);
}
DEVFN float eluf(float x){ return x>0.f ? x : (__expf(x)-1.f); }
DEVFN void softmax8(const float* gp, float* om){
  float g[8];
#pragma unroll
  for(int e=0;e<8;e++) g[e]=gp[e];
  float m=g[0];
#pragma unroll
  for(int e=1;e<8;e++) m=fmaxf(m,g[e]);
  float s=0.f;
#pragma unroll
  for(int e=0;e<8;e++){ om[e]=__expf(g[e]-m); s+=om[e]; }
  float inv=__fdividef(1.f,s);
#pragma unroll
  for(int e=0;e<8;e++) om[e]*=inv;
}

// ---------------- K1: gate GRU scan (blocks 0..31) + expert-1 GEMM (32..287) --
// Gate scan: 4 seqs/warp, 8 lanes/seq. Software-pipelined: in iteration t we
// compute layer2(t) and layer1(t+1) together (both consume bcast of h1(t)).
__global__ __launch_bounds__(256) void k1_gate_gemm(Params P)
{
  const int bid=blockIdx.x, tid=threadIdx.x;
  if (bid < 32) {
    if (bid==0 && tid>=32 && tid<96) g_stats[tid-32]=0.f;  // fresh stats each replay
    if (tid>=32) return;
    const int s = bid*4 + (tid>>3);        // seq 0..127 (0..63 Local, 64..127 Remote)
    const int j = tid & 7;                 // hidden unit
    const int b = s & 63;
    const float* T = ((s<64)? P.Local : P.Remote) + (size_t)b*128*132 + 128;

    float wxr[3],wxz[3],wxn[3];
#pragma unroll
    for(int k=0;k<3;k++){ wxr[k]=P.gWih0[j*3+k]; wxz[k]=P.gWih0[(8+j)*3+k]; wxn[k]=P.gWih0[(16+j)*3+k]; }
    const float bxr=P.gbih0[j], bxz=P.gbih0[8+j], bxn=P.gbih0[16+j];
    float whr[8],whz[8],whn[8];
#pragma unroll
    for(int k=0;k<8;k++){ whr[k]=P.gWhh0[j*8+k]; whz[k]=P.gWhh0[(8+j)*8+k]; whn[k]=P.gWhh0[(16+j)*8+k]; }
    const float bhr=P.gbhh0[j], bhz=P.gbhh0[8+j], bhn=P.gbhh0[16+j];
    float uir[8],uiz[8],uin[8];
#pragma unroll
    for(int k=0;k<8;k++){ uir[k]=P.gWih1[j*8+k]; uiz[k]=P.gWih1[(8+j)*8+k]; uin[k]=P.gWih1[(16+j)*8+k]; }
    const float bir=P.gbih1[j], biz=P.gbih1[8+j], bin_=P.gbih1[16+j];
    float vhr[8],vhz[8],vhn[8];
#pragma unroll
    for(int k=0;k<8;k++){ vhr[k]=P.gWhh1[j*8+k]; vhz[k]=P.gWhh1[(8+j)*8+k]; vhn[k]=P.gWhh1[(16+j)*8+k]; }
    const float cbr=P.gbhh1[j], cbz=P.gbhh1[8+j], cbn=P.gbhh1[16+j];

    // prologue: layer1 at t=0 (h1_prev = 0 -> hh matvec reduces to bias)
    float x0=T[0], x1=T[1], x2=T[2];
    {
      float ir=fmaf(wxr[2],x2,fmaf(wxr[1],x1,fmaf(wxr[0],x0,bxr)));
      float iz=fmaf(wxz[2],x2,fmaf(wxz[1],x1,fmaf(wxz[0],x0,bxz)));
      float in_=fmaf(wxn[2],x2,fmaf(wxn[1],x1,fmaf(wxn[0],x0,bxn)));
      float r=sigf(ir+bhr), z=sigf(iz+bhz), n=tanhf_(in_+r*bhn);
      x0=fmaf(z,-n,n); // reuse x0 as h1 temp
    }
    float h1=x0, h2=0.f;
    float* Gout = g_G + (size_t)s*128*8 + j;

    for (int t=0;t<128;t++){
      // broadcast current states
      float a1[8], a2[8];
#pragma unroll
      for(int k=0;k<8;k++){ a1[k]=__shfl_sync(0xffffffffu,h1,k,8); a2[k]=__shfl_sync(0xffffffffu,h2,k,8); }
      // prefetch x(t+1)
      float nx0=0.f,nx1=0.f,nx2=0.f;
      if (t<127){ const float* Tn=T+(size_t)(t+1)*132; nx0=Tn[0]; nx1=Tn[1]; nx2=Tn[2]; }
      // layer2(t): i2 = Wih1@a1 + bih1 ; q2 = Whh1@a2 + bhh1  (split accumulators)
      float i2r0=bir,i2z0=biz,i2n0=bin_, i2r1=0.f,i2z1=0.f,i2n1=0.f;
      float q2r0=cbr,q2z0=cbz,q2n0=cbn, q2r1=0.f,q2z1=0.f,q2n1=0.f;
#pragma unroll
      for(int k=0;k<4;k++){
        i2r0=fmaf(uir[k],a1[k],i2r0); i2z0=fmaf(uiz[k],a1[k],i2z0); i2n0=fmaf(uin[k],a1[k],i2n0);
        i2r1=fmaf(uir[k+4],a1[k+4],i2r1); i2z1=fmaf(uiz[k+4],a1[k+4],i2z1); i2n1=fmaf(uin[k+4],a1[k+4],i2n1);
        q2r0=fmaf(vhr[k],a2[k],q2r0); q2z0=fmaf(vhz[k],a2[k],q2z0); q2n0=fmaf(vhn[k],a2[k],q2n0);
        q2r1=fmaf(vhr[k+4],a2[k+4],q2r1); q2z1=fmaf(vhz[k+4],a2[k+4],q2z1); q2n1=fmaf(vhn[k+4],a2[k+4],q2n1);
      }
      // layer1(t+1): hh matvec from a1, ih from x(t+1)
      float hr0=bhr,hz0=bhz,hn0=bhn, hr1=0.f,hz1=0.f,hn1=0.f;
#pragma unroll
      for(int k=0;k<4;k++){
        hr0=fmaf(whr[k],a1[k],hr0); hz0=fmaf(whz[k],a1[k],hz0); hn0=fmaf(whn[k],a1[k],hn0);
        hr1=fmaf(whr[k+4],a1[k+4],hr1); hz1=fmaf(whz[k+4],a1[k+4],hz1); hn1=fmaf(whn[k+4],a1[k+4],hn1);
      }
      float ir=fmaf(wxr[2],nx2,fmaf(wxr[1],nx1,fmaf(wxr[0],nx0,bxr)));
      float iz=fmaf(wxz[2],nx2,fmaf(wxz[1],nx1,fmaf(wxz[0],nx0,bxz)));
      float in_=fmaf(wxn[2],nx2,fmaf(wxn[1],nx1,fmaf(wxn[0],nx0,bxn)));
      // activations: layer2(t)
      float r2=sigf((i2r0+i2r1)+(q2r0+q2r1));
      float z2=sigf((i2z0+i2z1)+(q2z0+q2z1));
      float n2=tanhf_((i2n0+i2n1)+r2*(q2n0+q2n1));
      h2=fmaf(z2,h2-n2,n2);
      Gout[(size_t)t*8]=h2;
      // activations: layer1(t+1)
      float r1=sigf(ir+hr0+hr1);
      float z1=sigf(iz+hz0+hz1);
      float n1=tanhf_(in_+r1*(hn0+hn1));
      h1=fmaf(z1,h1-n1,n1);
    }
    return;
  }
  // expert-1 GEMM: 64 rows x 128 cols per block
  {
    const int gb=bid-32, row0=gb*64;
    __shared__ float Xs[64][32];
    __shared__ float Ws[32][128];
    const int cg=tid&31, rg=tid>>5;
    float acc[8][4];
#pragma unroll
    for(int i=0;i<8;i++){acc[i][0]=0;acc[i][1]=0;acc[i][2]=0;acc[i][3]=0;}
    for (int kb=0;kb<128;kb+=32){
      for (int q=tid;q<512;q+=256){
        int r=q>>3, f4=q&7, row=row0+r;
        const float* xp=(row<8192)? (P.Local+(size_t)row*132) : (P.Remote+(size_t)(row-8192)*132);
        *(float4*)&Xs[r][f4*4] = *(const float4*)(xp+kb+f4*4);
      }
      for (int q=tid;q<1024;q+=256){
        int kk=q>>5, c=(q&31)*4, e=c>>4, h0=c&15;
        *(float4*)&Ws[kk][c] = *(const float4*)(P.aew1+(size_t)e*2048+(size_t)(kb+kk)*16+h0);
      }
      __syncthreads();
#pragma unroll
      for (int kk=0;kk<32;kk++){
        float4 w=*(float4*)&Ws[kk][cg*4];
#pragma unroll
        for(int i=0;i<8;i++){
          float x=Xs[rg*8+i][kk];
          acc[i][0]=fmaf(x,w.x,acc[i][0]); acc[i][1]=fmaf(x,w.y,acc[i][1]);
          acc[i][2]=fmaf(x,w.z,acc[i][2]); acc[i][3]=fmaf(x,w.w,acc[i][3]);
        }
      }
      __syncthreads();
    }
#pragma unroll
    for(int i=0;i<8;i++)
      *(float4*)&g_P[(size_t)(row0+rg*8+i)*128+cg*4] =
        make_float4(acc[i][0],acc[i][1],acc[i][2],acc[i][3]);
  }
}

// ---------------- K2: gated mix + BN stats ----------------------------------
__global__ __launch_bounds__(256) void k2_mix(Params P)
{
  const int tid=threadIdx.x;
  const int rowbase=blockIdx.x*128;
  const int call=rowbase>>13;
  const int hh=tid&15;
  float s1=0.f,s2=0.f;
  for (int pass=0;pass<8;pass++){
    const int row=rowbase+pass*16+(tid>>4);
    const int rr=row&8191, bb=rr>>7, w=rr&127;
    const float* gp=g_G+((size_t)(call*64+bb)*128+w)*8;
    float om[8]; softmax8(gp,om);
    const float* pp=g_P+(size_t)row*128+hh;
    float h=0.f;
#pragma unroll
    for(int e=0;e<8;e++) h=fmaf(om[e], pp[e*16]+P.aeb1[e*16+hh], h);
    g_H[(size_t)row*16+hh]=h;
    s1+=h; s2=fmaf(h,h,s2);
  }
  __shared__ float red[256];
  red[tid]=s1; __syncthreads();
  for(int off=128;off>=16;off>>=1){ if(tid<off) red[tid]+=red[tid+off]; __syncthreads(); }
  if(tid<16) atomicAdd(&g_stats[call*32+tid], red[tid]);
  __syncthreads();
  red[tid]=s2; __syncthreads();
  for(int off=128;off>=16;off>>=1){ if(tid<off) red[tid]+=red[tid+off]; __syncthreads(); }
  if(tid<16) atomicAdd(&g_stats[call*32+16+tid], red[tid]);
}

// ---------------- K3: BN+ELU+expert2; Z=ZL+ZR; mixer input proj -------------
__global__ __launch_bounds__(256) void k3_z(Params P)
{
  __shared__ float sw2[2048], sb2[128], sWm[768], sbm[48], sg[16], sbt[16];
  __shared__ float smean[32], srstd[32];
  __shared__ float zbuf[256*17];
  const int tid=threadIdx.x;
  for(int i=tid;i<2048;i+=256) sw2[i]=P.aew2[i];
  for(int i=tid;i<768;i+=256)  sWm[i]=P.mWih0[i];
  if(tid<128) sb2[tid]=P.aeb2[tid];
  if(tid<48)  sbm[tid]=P.mbih0[tid];
  if(tid<16){ sg[tid]=P.aeg[tid]; sbt[tid]=P.aebt[tid]; }
  if(tid<32){
    int c=tid>>4, hh=tid&15;
    float s1=g_stats[c*32+hh], s2=g_stats[c*32+16+hh];
    float m=s1*(1.f/8192.f), v=s2*(1.f/8192.f)-m*m;
    smean[tid]=m; srstd[tid]=rsqrtf(v+1e-5f);
  }
  __syncthreads();
  const int p=blockIdx.x*128+(tid&127);
  const int call=tid>>7;
  const int b=p>>7, w=p&127;
  const int row=call*8192+p;
  const float* gp=g_G+((size_t)(call*64+b)*128+w)*8;
  float om[8]; softmax8(gp,om);
  float a[16];
#pragma unroll
  for(int hh=0;hh<16;hh++){
    float h=g_H[(size_t)row*16+hh];
    a[hh]=eluf(sg[hh]*(h-smean[call*16+hh])*srstd[call*16+hh]+sbt[hh]);
  }
  float z[16];
#pragma unroll
  for(int o=0;o<16;o++) z[o]=0.f;
#pragma unroll
  for(int e=0;e<8;e++){
    float we=om[e];
#pragma unroll
    for(int o=0;o<16;o++){
      float acc=sb2[e*16+o];
#pragma unroll
      for(int hh=0;hh<16;hh++) acc=fmaf(a[hh], sw2[e*256+hh*16+o], acc);
      z[o]=fmaf(we,acc,z[o]);
    }
  }
#pragma unroll
  for(int o=0;o<16;o++) zbuf[tid*17+o]=z[o];
  __syncthreads();
  if(tid<128){
    const int pp=blockIdx.x*128+tid;
    float Z[16];
#pragma unroll
    for(int o=0;o<16;o++) Z[o]=zbuf[tid*17+o]+zbuf[(tid+128)*17+o];
    float* xo=g_XW0+(size_t)pp*48;
#pragma unroll
    for(int i=0;i<48;i++){
      float acc=sbm[i];
#pragma unroll
      for(int o=0;o<16;o++) acc=fmaf(sWm[i*16+o],Z[o],acc);
      xo[i]=acc;
    }
  }
}

// ---------------- K4: mixer GRU scan (2 seqs/warp, 16 lanes/seq) ------------
// Software-pipelined: iteration t computes layer2(t) and layer1(t+1) together,
// both from bcast(h1(t)) — activations and matvecs of the two layers overlap.
__global__ __launch_bounds__(32,1) void k4_mgru(Params P)
{
  const int lane=threadIdx.x;
  const int s=blockIdx.x*2+(lane>>4);
  const int j=lane&15;
  float w0r[16],w0z[16],w0n[16];
#pragma unroll
  for(int k=0;k<16;k++){ w0r[k]=P.mWhh0[j*16+k]; w0z[k]=P.mWhh0[(16+j)*16+k]; w0n[k]=P.mWhh0[(32+j)*16+k]; }
  const float b0r=P.mbhh0[j], b0z=P.mbhh0[16+j], b0n=P.mbhh0[32+j];
  float uir[16],uiz[16],uin[16];
#pragma unroll
  for(int k=0;k<16;k++){ uir[k]=P.mWih1[j*16+k]; uiz[k]=P.mWih1[(16+j)*16+k]; uin[k]=P.mWih1[(32+j)*16+k]; }
  const float bir=P.mbih1[j], biz=P.mbih1[16+j], bin_=P.mbih1[32+j];
  float vhr[16],vhz[16],vhn[16];
#pragma unroll
  for(int k=0;k<16;k++){ vhr[k]=P.mWhh1[j*16+k]; vhz[k]=P.mWhh1[(16+j)*16+k]; vhn[k]=P.mWhh1[(32+j)*16+k]; }
  const float cbr=P.mbhh1[j], cbz=P.mbhh1[16+j], cbn=P.mbhh1[32+j];

  const float* xp=g_XW0+(size_t)s*128*48;
  // prologue: layer1 at t=0 (h1_prev = 0)
  float h1,h2=0.f;
  {
    float xr=xp[j], xz=xp[16+j], xn=xp[32+j];   // include bih0 already
    float r=sigf(xr+b0r), z=sigf(xz+b0z), n=tanhf_(xn+r*b0n);
    h1=fmaf(z,-n,n);
  }
  for (int t=0;t<128;t++){
    float a1[16], a2[16];
#pragma unroll
    for(int k=0;k<16;k++){ a1[k]=__shfl_sync(0xffffffffu,h1,k,16); a2[k]=__shfl_sync(0xffffffffu,h2,k,16); }
    float nxr=0.f,nxz=0.f,nxn=0.f;
    if(t<127){ const float* q=xp+(size_t)(t+1)*48; nxr=q[j]; nxz=q[16+j]; nxn=q[32+j]; }
    // layer2(t): i2 = Wih1@a1 + bih1 ; q2 = Whh1@a2 + bhh1 (split accumulators)
    float i2r0=bir,i2z0=biz,i2n0=bin_, i2r1=0.f,i2z1=0.f,i2n1=0.f;
    float q2r0=cbr,q2z0=cbz,q2n0=cbn, q2r1=0.f,q2z1=0.f,q2n1=0.f;
#pragma unroll
    for(int k=0;k<8;k++){
      i2r0=fmaf(uir[k],a1[k],i2r0); i2z0=fmaf(uiz[k],a1[k],i2z0); i2n0=fmaf(uin[k],a1[k],i2n0);
      i2r1=fmaf(uir[k+8],a1[k+8],i2r1); i2z1=fmaf(uiz[k+8],a1[k+8],i2z1); i2n1=fmaf(uin[k+8],a1[k+8],i2n1);
      q2r0=fmaf(vhr[k],a2[k],q2r0); q2z0=fmaf(vhz[k],a2[k],q2z0); q2n0=fmaf(vhn[k],a2[k],q2n0);
      q2r1=fmaf(vhr[k+8],a2[k+8],q2r1); q2z1=fmaf(vhz[k+8],a2[k+8],q2z1); q2n1=fmaf(vhn[k+8],a2[k+8],q2n1);
    }
    // layer1(t+1): hh matvec from a1
    float hr0=b0r,hz0=b0z,hn0=b0n, hr1=0.f,hz1=0.f,hn1=0.f;
#pragma unroll
    for(int k=0;k<8;k++){
      hr0=fmaf(w0r[k],a1[k],hr0); hz0=fmaf(w0z[k],a1[k],hz0); hn0=fmaf(w0n[k],a1[k],hn0);
      hr1=fmaf(w0r[k+8],a1[k+8],hr1); hz1=fmaf(w0z[k+8],a1[k+8],hz1); hn1=fmaf(w0n[k+8],a1[k+8],hn1);
    }
    // activations layer2(t)
    float r2=sigf((i2r0+i2r1)+(q2r0+q2r1));
    float z2=sigf((i2z0+i2z1)+(q2z0+q2z1));
    float n2=tanhf_((i2n0+i2n1)+r2*(q2n0+q2n1));
    h2=fmaf(z2,h2-n2,n2);
    // activations layer1(t+1)
    float r1=sigf(nxr+hr0+hr1);
    float z1=sigf(nxz+hz0+hz1);
    float n1=tanhf_(nxn+r1*(hn0+hn1));
    h1=fmaf(z1,h1-n1,n1);
  }
  g_HF[s*16+j]=h2;
}

// ---------------- K5: decoder expert (one block) ----------------------------
__global__ __launch_bounds__(1024) void k5_dec(Params P)
{
  __shared__ float om_s[64*8], x_s[64*17], a_s[64*16], ms[16], rs[16];
  const int tid=threadIdx.x;
  const int b=tid>>4, hh=tid&15;
  if (tid<64){
    const float* gp=g_G+((size_t)(64+tid)*128+127)*8;
    float om[8]; softmax8(gp,om);
#pragma unroll
    for(int e=0;e<8;e++) om_s[tid*8+e]=om[e];
    x_s[tid*17+16]=P.Remote[(size_t)tid*128*132+127*132+131];
  }
  x_s[b*17+hh]=g_HF[b*16+hh];
  __syncthreads();
  {
    float h=0.f;
#pragma unroll
    for(int e=0;e<8;e++){
      float acc=P.mdb1[e*16+hh];
#pragma unroll
      for(int i=0;i<17;i++) acc=fmaf(x_s[b*17+i], P.mdw1[e*272+i*16+hh], acc);
      h=fmaf(om_s[b*8+e],acc,h);
    }
    a_s[b*16+hh]=h;
  }
  __syncthreads();
  if (tid<16){
    float s1=0.f,s2=0.f;
    for(int bb=0;bb<64;bb++){ float v=a_s[bb*16+tid]; s1+=v; s2=fmaf(v,v,s2); }
    float m=s1*(1.f/64.f), v=s2*(1.f/64.f)-m*m;
    ms[tid]=m; rs[tid]=rsqrtf(v+1e-5f);
  }
  __syncthreads();
  {
    float h=a_s[b*16+hh];
    a_s[b*16+hh]=eluf(P.mdg[hh]*(h-ms[hh])*rs[hh]+P.mdbt[hh]);
  }
  __syncthreads();
  for (int q=tid;q<8192;q+=1024){
    int bb=q>>7, o=q&127;
    float r=0.f;
#pragma unroll
    for(int e=0;e<8;e++){
      float acc=P.mdb2[e*128+o];
#pragma unroll
      for(int k=0;k<16;k++) acc=fmaf(a_s[bb*16+k], P.mdw2[e*2048+k*128+o], acc);
      r=fmaf(om_s[bb*8+e],acc,r);
    }
    P.out[q]=r;
  }
}

extern "C" void kernel_launch(void* const* d_in, const int* in_sizes, int n_in,
                              void* d_out, int out_size)
{
  Params P;
  const float** f = (const float**)d_in;
  P.Local=f[0]; P.Remote=f[1];
  P.gWih0=f[2]; P.gWhh0=f[3]; P.gbih0=f[4]; P.gbhh0=f[5];
  P.gWih1=f[6]; P.gWhh1=f[7]; P.gbih1=f[8]; P.gbhh1=f[9];
  if (in_sizes[10] == 16384) {
    P.aew1=f[10]; P.aeb1=f[11]; P.aew2=f[12]; P.aeb2=f[13]; P.aeg=f[14]; P.aebt=f[15];
    P.mdw1=f[16]; P.mdb1=f[17]; P.mdw2=f[18]; P.mdb2=f[19]; P.mdg=f[20]; P.mdbt=f[21];
    P.mWih0=f[22]; P.mWhh0=f[23]; P.mbih0=f[24]; P.mbhh0=f[25];
    P.mWih1=f[26]; P.mWhh1=f[27]; P.mbih1=f[28]; P.mbhh1=f[29];
  } else {
    P.mWih0=f[10]; P.mWhh0=f[11]; P.mbih0=f[12]; P.mbhh0=f[13];
    P.mWih1=f[14]; P.mWhh1=f[15]; P.mbih1=f[16]; P.mbhh1=f[17];
    P.aew1=f[18]; P.aeb1=f[19]; P.aew2=f[20]; P.aeb2=f[21]; P.aeg=f[22]; P.aebt=f[23];
    P.mdw1=f[24]; P.mdb1=f[25]; P.mdw2=f[26]; P.mdb2=f[27]; P.mdg=f[28]; P.mdbt=f[29];
  }
  P.out=(float*)d_out;

  k1_gate_gemm<<<288,256>>>(P);
  k2_mix<<<128,256>>>(P);
  k3_z<<<64,256>>>(P);
  k4_mgru<<<32,32>>>(P);
  k5_dec<<<1,1024>>>(P);
}

// round 9
// speedup vs baseline: 1.1671x; 1.1671x over previous
#include <cuda_runtime.h>
#include <math.h>

// E=8 A=128 TGT=3 HID=16 OUT=128 B=64 W=128 F=132
struct Params {
  const float *Local, *Remote;
  const float *gWih0,*gWhh0,*gbih0,*gbhh0,*gWih1,*gWhh1,*gbih1,*gbhh1;
  const float *aew1,*aeb1,*aew2,*aeb2,*aeg,*aebt;
  const float *mdw1,*mdb1,*mdw2,*mdb2,*mdg,*mdbt;
  const float *mWih0,*mWhh0,*mbih0,*mbhh0,*mWih1,*mWhh1,*mbih1,*mbhh1;
  float* out;
};

__device__ __align__(16) float g_G[128*128*8];   // gate GRU hidden (pre-softmax) [seq][t][8]
__device__ __align__(16) float g_P[16384*128];   // expert-1 GEMM result
__device__ __align__(16) float g_H[16384*16];    // mixed hidden (pre-BN)
__device__             float g_stats[64];        // [call*32 + (sum16|sumsq16)]
__device__ __align__(16) float g_XW0[8192*48];   // mixer layer0 input projection (incl. bih0)
__device__ __align__(16) float g_HF[64*16];      // mixer final hidden

#define DEVFN __device__ __forceinline__
typedef unsigned long long u64;

DEVFN u64 pk2(float lo,float hi){u64 r;asm("mov.b64 %0,{%1,%2};":"=l"(r):"f"(lo),"f"(hi));return r;}
DEVFN float hadd2(u64 v){float lo,hi;asm("mov.b64 {%0,%1},%2;":"=f"(lo),"=f"(hi):"l"(v));return lo+hi;}
DEVFN u64 fma2(u64 a,u64 b,u64 c){u64 d;asm("fma.rn.f32x2 %0,%1,%2,%3;":"=l"(d):"l"(a),"l"(b),"l"(c));return d;}
DEVFN u64 add2(u64 a,u64 b){u64 d;asm("add.rn.f32x2 %0,%1,%2;":"=l"(d):"l"(a),"l"(b));return d;}
DEVFN float tanha(float x){float y;asm("tanh.approx.f32 %0,%1;":"=f"(y):"f"(x));return y;}
DEVFN float sigt(float x){ return fmaf(tanha(0.5f*x),0.5f,0.5f); }

DEVFN float eluf(float x){ return x>0.f ? x : (__expf(x)-1.f); }
DEVFN void softmax8(const float* gp, float* om){
  float g[8];
#pragma unroll
  for(int e=0;e<8;e++) g[e]=gp[e];
  float m=g[0];
#pragma unroll
  for(int e=1;e<8;e++) m=fmaxf(m,g[e]);
  float s=0.f;
#pragma unroll
  for(int e=0;e<8;e++){ om[e]=__expf(g[e]-m); s+=om[e]; }
  float inv=__fdividef(1.f,s);
#pragma unroll
  for(int e=0;e<8;e++) om[e]*=inv;
}

// ---------------- K1: gate GRU scan (blocks 0..31) + expert-1 GEMM (32..287) --
// Gate scan: 4 seqs/warp, 8 lanes/seq. smem h-broadcast (double-buffered),
// f32x2 packed dot products, tanh.approx activations, cross-layer pipelining.
__global__ __launch_bounds__(256) void k1_gate_gemm(Params P)
{
  __shared__ __align__(16) float sb[2][2][4][8];     // [buf][h1|h2][seqInWarp][unit]
  __shared__ float Xs[64][32];
  __shared__ float Ws[32][128];

  const int bid=blockIdx.x, tid=threadIdx.x;
  if (bid < 32) {
    if (bid==0 && tid>=32 && tid<96) g_stats[tid-32]=0.f;  // fresh stats each replay
    if (tid>=32) return;
    const int sw = tid>>3;                 // seq in warp 0..3
    const int s  = bid*4 + sw;             // seq 0..127 (0..63 Local, 64..127 Remote)
    const int j  = tid & 7;                // hidden unit
    const int b  = s & 63;
    const float* T = ((s<64)? P.Local : P.Remote) + (size_t)b*128*132 + 128;

    // ih layer0 (scalar, input dim 3)
    float wxr0=P.gWih0[j*3+0],wxr1=P.gWih0[j*3+1],wxr2=P.gWih0[j*3+2];
    float wxz0=P.gWih0[(8+j)*3+0],wxz1=P.gWih0[(8+j)*3+1],wxz2=P.gWih0[(8+j)*3+2];
    float wxn0=P.gWih0[(16+j)*3+0],wxn1=P.gWih0[(16+j)*3+1],wxn2=P.gWih0[(16+j)*3+2];
    const float bxr=P.gbih0[j], bxz=P.gbih0[8+j], bxn=P.gbih0[16+j];
    // packed hh layer0
    u64 whrp[4],whzp[4],whnp[4];
#pragma unroll
    for(int k=0;k<4;k++){
      whrp[k]=pk2(P.gWhh0[j*8+2*k],P.gWhh0[j*8+2*k+1]);
      whzp[k]=pk2(P.gWhh0[(8+j)*8+2*k],P.gWhh0[(8+j)*8+2*k+1]);
      whnp[k]=pk2(P.gWhh0[(16+j)*8+2*k],P.gWhh0[(16+j)*8+2*k+1]);
    }
    const u64 bhrp=pk2(P.gbhh0[j],0.f), bhzp=pk2(P.gbhh0[8+j],0.f), bhnp=pk2(P.gbhh0[16+j],0.f);
    // packed ih layer1
    u64 uirp[4],uizp[4],uinp[4];
#pragma unroll
    for(int k=0;k<4;k++){
      uirp[k]=pk2(P.gWih1[j*8+2*k],P.gWih1[j*8+2*k+1]);
      uizp[k]=pk2(P.gWih1[(8+j)*8+2*k],P.gWih1[(8+j)*8+2*k+1]);
      uinp[k]=pk2(P.gWih1[(16+j)*8+2*k],P.gWih1[(16+j)*8+2*k+1]);
    }
    const u64 birp=pk2(P.gbih1[j],0.f), bizp=pk2(P.gbih1[8+j],0.f), binp=pk2(P.gbih1[16+j],0.f);
    // packed hh layer1
    u64 vhrp[4],vhzp[4],vhnp[4];
#pragma unroll
    for(int k=0;k<4;k++){
      vhrp[k]=pk2(P.gWhh1[j*8+2*k],P.gWhh1[j*8+2*k+1]);
      vhzp[k]=pk2(P.gWhh1[(8+j)*8+2*k],P.gWhh1[(8+j)*8+2*k+1]);
      vhnp[k]=pk2(P.gWhh1[(16+j)*8+2*k],P.gWhh1[(16+j)*8+2*k+1]);
    }
    const u64 cbrp=pk2(P.gbhh1[j],0.f), cbzp=pk2(P.gbhh1[8+j],0.f), cbnp=pk2(P.gbhh1[16+j],0.f);
    const float bhr_s=P.gbhh0[j], bhz_s=P.gbhh0[8+j], bhn_s=P.gbhh0[16+j];

    // prologue: layer1 at t=0 (h1_prev = 0 -> hh matvec reduces to bias)
    float h1,h2=0.f;
    {
      float x0=T[0],x1=T[1],x2=T[2];
      float ir=fmaf(wxr2,x2,fmaf(wxr1,x1,fmaf(wxr0,x0,bxr)));
      float iz=fmaf(wxz2,x2,fmaf(wxz1,x1,fmaf(wxz0,x0,bxz)));
      float in_=fmaf(wxn2,x2,fmaf(wxn1,x1,fmaf(wxn0,x0,bxn)));
      float r=sigt(ir+bhr_s), z=sigt(iz+bhz_s), n=tanha(fmaf(r,bhn_s,in_));
      h1=fmaf(z,-n,n);
    }
    float* Gout = g_G + (size_t)s*128*8 + j;

    for (int t=0;t<128;t++){
      const int buf=t&1;
      sb[buf][0][sw][j]=h1; sb[buf][1][sw][j]=h2;
      __syncwarp();
      const ulonglong2* p1=(const ulonglong2*)&sb[buf][0][sw][0];
      const ulonglong2* p2=(const ulonglong2*)&sb[buf][1][sw][0];
      ulonglong2 v10=p1[0], v11=p1[1], v20=p2[0], v21=p2[1];
      u64 A1[4]={v10.x,v10.y,v11.x,v11.y};
      u64 A2[4]={v20.x,v20.y,v21.x,v21.y};
      // prefetch x(t+1)
      float nx0=0.f,nx1=0.f,nx2=0.f;
      if (t<127){ const float* Tn=T+(size_t)(t+1)*132; nx0=Tn[0]; nx1=Tn[1]; nx2=Tn[2]; }
      // packed dots: layer2 (i2 from A1, q2 from A2) + layer1 hh (from A1)
      u64 i2r=birp,i2z=bizp,i2n=binp;
      u64 q2r=cbrp,q2z=cbzp,q2n=cbnp;
      u64 hr=bhrp, hz=bhzp, hn=bhnp;
#pragma unroll
      for(int k=0;k<4;k++){
        i2r=fma2(uirp[k],A1[k],i2r); i2z=fma2(uizp[k],A1[k],i2z); i2n=fma2(uinp[k],A1[k],i2n);
        q2r=fma2(vhrp[k],A2[k],q2r); q2z=fma2(vhzp[k],A2[k],q2z); q2n=fma2(vhnp[k],A2[k],q2n);
        hr =fma2(whrp[k],A1[k],hr ); hz =fma2(whzp[k],A1[k],hz ); hn =fma2(whnp[k],A1[k],hn );
      }
      float ir=fmaf(wxr2,nx2,fmaf(wxr1,nx1,fmaf(wxr0,nx0,bxr)));
      float iz=fmaf(wxz2,nx2,fmaf(wxz1,nx1,fmaf(wxz0,nx0,bxz)));
      float in_=fmaf(wxn2,nx2,fmaf(wxn1,nx1,fmaf(wxn0,nx0,bxn)));
      // activations layer2(t)
      float r2=sigt(hadd2(add2(i2r,q2r)));
      float z2=sigt(hadd2(add2(i2z,q2z)));
      float n2=tanha(fmaf(r2,hadd2(q2n),hadd2(i2n)));
      h2=fmaf(z2,h2-n2,n2);
      Gout[(size_t)t*8]=h2;
      // activations layer1(t+1)
      float r1=sigt(ir+hadd2(hr));
      float z1=sigt(iz+hadd2(hz));
      float n1=tanha(fmaf(r1,hadd2(hn),in_));
      h1=fmaf(z1,h1-n1,n1);
    }
    return;
  }
  // expert-1 GEMM: 64 rows x 128 cols per block
  {
    const int gb=bid-32, row0=gb*64;
    const int cg=tid&31, rg=tid>>5;
    float acc[8][4];
#pragma unroll
    for(int i=0;i<8;i++){acc[i][0]=0;acc[i][1]=0;acc[i][2]=0;acc[i][3]=0;}
    for (int kb=0;kb<128;kb+=32){
      for (int q=tid;q<512;q+=256){
        int r=q>>3, f4=q&7, row=row0+r;
        const float* xp=(row<8192)? (P.Local+(size_t)row*132) : (P.Remote+(size_t)(row-8192)*132);
        *(float4*)&Xs[r][f4*4] = *(const float4*)(xp+kb+f4*4);
      }
      for (int q=tid;q<1024;q+=256){
        int kk=q>>5, c=(q&31)*4, e=c>>4, h0=c&15;
        *(float4*)&Ws[kk][c] = *(const float4*)(P.aew1+(size_t)e*2048+(size_t)(kb+kk)*16+h0);
      }
      __syncthreads();
#pragma unroll
      for (int kk=0;kk<32;kk++){
        float4 w=*(float4*)&Ws[kk][cg*4];
#pragma unroll
        for(int i=0;i<8;i++){
          float x=Xs[rg*8+i][kk];
          acc[i][0]=fmaf(x,w.x,acc[i][0]); acc[i][1]=fmaf(x,w.y,acc[i][1]);
          acc[i][2]=fmaf(x,w.z,acc[i][2]); acc[i][3]=fmaf(x,w.w,acc[i][3]);
        }
      }
      __syncthreads();
    }
#pragma unroll
    for(int i=0;i<8;i++)
      *(float4*)&g_P[(size_t)(row0+rg*8+i)*128+cg*4] =
        make_float4(acc[i][0],acc[i][1],acc[i][2],acc[i][3]);
  }
}

// ---------------- K2: gated mix + BN stats ----------------------------------
__global__ __launch_bounds__(256) void k2_mix(Params P)
{
  const int tid=threadIdx.x;
  const int rowbase=blockIdx.x*128;
  const int call=rowbase>>13;
  const int hh=tid&15;
  float s1=0.f,s2=0.f;
  for (int pass=0;pass<8;pass++){
    const int row=rowbase+pass*16+(tid>>4);
    const int rr=row&8191, bb=rr>>7, w=rr&127;
    const float* gp=g_G+((size_t)(call*64+bb)*128+w)*8;
    float om[8]; softmax8(gp,om);
    const float* pp=g_P+(size_t)row*128+hh;
    float h=0.f;
#pragma unroll
    for(int e=0;e<8;e++) h=fmaf(om[e], pp[e*16]+P.aeb1[e*16+hh], h);
    g_H[(size_t)row*16+hh]=h;
    s1+=h; s2=fmaf(h,h,s2);
  }
  __shared__ float red[256];
  red[tid]=s1; __syncthreads();
  for(int off=128;off>=16;off>>=1){ if(tid<off) red[tid]+=red[tid+off]; __syncthreads(); }
  if(tid<16) atomicAdd(&g_stats[call*32+tid], red[tid]);
  __syncthreads();
  red[tid]=s2; __syncthreads();
  for(int off=128;off>=16;off>>=1){ if(tid<off) red[tid]+=red[tid+off]; __syncthreads(); }
  if(tid<16) atomicAdd(&g_stats[call*32+16+tid], red[tid]);
}

// ---------------- K3: BN+ELU+expert2; Z=ZL+ZR; mixer input proj -------------
__global__ __launch_bounds__(256) void k3_z(Params P)
{
  __shared__ float sw2[2048], sb2[128], sWm[768], sbm[48], sg[16], sbt[16];
  __shared__ float smean[32], srstd[32];
  __shared__ float zbuf[256*17];
  const int tid=threadIdx.x;
  for(int i=tid;i<2048;i+=256) sw2[i]=P.aew2[i];
  for(int i=tid;i<768;i+=256)  sWm[i]=P.mWih0[i];
  if(tid<128) sb2[tid]=P.aeb2[tid];
  if(tid<48)  sbm[tid]=P.mbih0[tid];
  if(tid<16){ sg[tid]=P.aeg[tid]; sbt[tid]=P.aebt[tid]; }
  if(tid<32){
    int c=tid>>4, hh=tid&15;
    float s1=g_stats[c*32+hh], s2=g_stats[c*32+16+hh];
    float m=s1*(1.f/8192.f), v=s2*(1.f/8192.f)-m*m;
    smean[tid]=m; srstd[tid]=rsqrtf(v+1e-5f);
  }
  __syncthreads();
  const int p=blockIdx.x*128+(tid&127);
  const int call=tid>>7;
  const int b=p>>7, w=p&127;
  const int row=call*8192+p;
  const float* gp=g_G+((size_t)(call*64+b)*128+w)*8;
  float om[8]; softmax8(gp,om);
  float a[16];
#pragma unroll
  for(int hh=0;hh<16;hh++){
    float h=g_H[(size_t)row*16+hh];
    a[hh]=eluf(sg[hh]*(h-smean[call*16+hh])*srstd[call*16+hh]+sbt[hh]);
  }
  float z[16];
#pragma unroll
  for(int o=0;o<16;o++) z[o]=0.f;
#pragma unroll
  for(int e=0;e<8;e++){
    float we=om[e];
#pragma unroll
    for(int o=0;o<16;o++){
      float acc=sb2[e*16+o];
#pragma unroll
      for(int hh=0;hh<16;hh++) acc=fmaf(a[hh], sw2[e*256+hh*16+o], acc);
      z[o]=fmaf(we,acc,z[o]);
    }
  }
#pragma unroll
  for(int o=0;o<16;o++) zbuf[tid*17+o]=z[o];
  __syncthreads();
  if(tid<128){
    const int pp=blockIdx.x*128+tid;
    float Z[16];
#pragma unroll
    for(int o=0;o<16;o++) Z[o]=zbuf[tid*17+o]+zbuf[(tid+128)*17+o];
    float* xo=g_XW0+(size_t)pp*48;
#pragma unroll
    for(int i=0;i<48;i++){
      float acc=sbm[i];
#pragma unroll
      for(int o=0;o<16;o++) acc=fmaf(sWm[i*16+o],Z[o],acc);
      xo[i]=acc;
    }
  }
}

// ---------------- K4: mixer GRU scan (2 seqs/warp, 16 lanes/seq) ------------
// smem h-broadcast (double-buffered), f32x2 packed dots, tanh.approx acts,
// cross-layer pipelining (layer2(t) together with layer1(t+1)).
__global__ __launch_bounds__(32,1) void k4_mgru(Params P)
{
  __shared__ __align__(16) float sb[2][2][2][16];   // [buf][h1|h2][seqInWarp][unit]
  const int lane=threadIdx.x;
  const int sw=lane>>4;
  const int s=blockIdx.x*2+sw;
  const int j=lane&15;

  u64 w0rp[8],w0zp[8],w0np[8];
#pragma unroll
  for(int k=0;k<8;k++){
    w0rp[k]=pk2(P.mWhh0[j*16+2*k],P.mWhh0[j*16+2*k+1]);
    w0zp[k]=pk2(P.mWhh0[(16+j)*16+2*k],P.mWhh0[(16+j)*16+2*k+1]);
    w0np[k]=pk2(P.mWhh0[(32+j)*16+2*k],P.mWhh0[(32+j)*16+2*k+1]);
  }
  const u64 b0rp=pk2(P.mbhh0[j],0.f), b0zp=pk2(P.mbhh0[16+j],0.f), b0np=pk2(P.mbhh0[32+j],0.f);
  const float b0r_s=P.mbhh0[j], b0z_s=P.mbhh0[16+j], b0n_s=P.mbhh0[32+j];
  u64 uirp[8],uizp[8],uinp[8];
#pragma unroll
  for(int k=0;k<8;k++){
    uirp[k]=pk2(P.mWih1[j*16+2*k],P.mWih1[j*16+2*k+1]);
    uizp[k]=pk2(P.mWih1[(16+j)*16+2*k],P.mWih1[(16+j)*16+2*k+1]);
    uinp[k]=pk2(P.mWih1[(32+j)*16+2*k],P.mWih1[(32+j)*16+2*k+1]);
  }
  const u64 birp=pk2(P.mbih1[j],0.f), bizp=pk2(P.mbih1[16+j],0.f), binp=pk2(P.mbih1[32+j],0.f);
  u64 vhrp[8],vhzp[8],vhnp[8];
#pragma unroll
  for(int k=0;k<8;k++){
    vhrp[k]=pk2(P.mWhh1[j*16+2*k],P.mWhh1[j*16+2*k+1]);
    vhzp[k]=pk2(P.mWhh1[(16+j)*16+2*k],P.mWhh1[(16+j)*16+2*k+1]);
    vhnp[k]=pk2(P.mWhh1[(32+j)*16+2*k],P.mWhh1[(32+j)*16+2*k+1]);
  }
  const u64 cbrp=pk2(P.mbhh1[j],0.f), cbzp=pk2(P.mbhh1[16+j],0.f), cbnp=pk2(P.mbhh1[32+j],0.f);

  const float* xp=g_XW0+(size_t)s*128*48;
  // prologue: layer1 at t=0 (h1_prev = 0)
  float h1,h2=0.f;
  {
    float xr=xp[j], xz=xp[16+j], xn=xp[32+j];   // include bih0 already
    float r=sigt(xr+b0r_s), z=sigt(xz+b0z_s), n=tanha(fmaf(r,b0n_s,xn));
    h1=fmaf(z,-n,n);
  }
  for (int t=0;t<128;t++){
    const int buf=t&1;
    sb[buf][0][sw][j]=h1; sb[buf][1][sw][j]=h2;
    __syncwarp();
    const ulonglong2* p1=(const ulonglong2*)&sb[buf][0][sw][0];
    const ulonglong2* p2=(const ulonglong2*)&sb[buf][1][sw][0];
    ulonglong2 v10=p1[0], v11=p1[1], v12=p1[2], v13=p1[3];
    ulonglong2 v20=p2[0], v21=p2[1], v22=p2[2], v23=p2[3];
    u64 A1[8]={v10.x,v10.y,v11.x,v11.y,v12.x,v12.y,v13.x,v13.y};
    u64 A2[8]={v20.x,v20.y,v21.x,v21.y,v22.x,v22.y,v23.x,v23.y};
    float nxr=0.f,nxz=0.f,nxn=0.f;
    if(t<127){ const float* q=xp+(size_t)(t+1)*48; nxr=q[j]; nxz=q[16+j]; nxn=q[32+j]; }
    u64 i2r=birp,i2z=bizp,i2n=binp;
    u64 q2r=cbrp,q2z=cbzp,q2n=cbnp;
    u64 hr=b0rp, hz=b0zp, hn=b0np;
#pragma unroll
    for(int k=0;k<8;k++){
      i2r=fma2(uirp[k],A1[k],i2r); i2z=fma2(uizp[k],A1[k],i2z); i2n=fma2(uinp[k],A1[k],i2n);
      q2r=fma2(vhrp[k],A2[k],q2r); q2z=fma2(vhzp[k],A2[k],q2z); q2n=fma2(vhnp[k],A2[k],q2n);
      hr =fma2(w0rp[k],A1[k],hr ); hz =fma2(w0zp[k],A1[k],hz ); hn =fma2(w0np[k],A1[k],hn );
    }
    // activations layer2(t)
    float r2=sigt(hadd2(add2(i2r,q2r)));
    float z2=sigt(hadd2(add2(i2z,q2z)));
    float n2=tanha(fmaf(r2,hadd2(q2n),hadd2(i2n)));
    h2=fmaf(z2,h2-n2,n2);
    // activations layer1(t+1)
    float r1=sigt(nxr+hadd2(hr));
    float z1=sigt(nxz+hadd2(hz));
    float n1=tanha(fmaf(r1,hadd2(hn),nxn));
    h1=fmaf(z1,h1-n1,n1);
  }
  g_HF[s*16+j]=h2;
}

// ---------------- K5: decoder expert (one block) ----------------------------
__global__ __launch_bounds__(1024) void k5_dec(Params P)
{
  __shared__ float om_s[64*8], x_s[64*17], a_s[64*16], ms[16], rs[16];
  const int tid=threadIdx.x;
  const int b=tid>>4, hh=tid&15;
  if (tid<64){
    const float* gp=g_G+((size_t)(64+tid)*128+127)*8;
    float om[8]; softmax8(gp,om);
#pragma unroll
    for(int e=0;e<8;e++) om_s[tid*8+e]=om[e];
    x_s[tid*17+16]=P.Remote[(size_t)tid*128*132+127*132+131];
  }
  x_s[b*17+hh]=g_HF[b*16+hh];
  __syncthreads();
  {
    float h=0.f;
#pragma unroll
    for(int e=0;e<8;e++){
      float acc=P.mdb1[e*16+hh];
#pragma unroll
      for(int i=0;i<17;i++) acc=fmaf(x_s[b*17+i], P.mdw1[e*272+i*16+hh], acc);
      h=fmaf(om_s[b*8+e],acc,h);
    }
    a_s[b*16+hh]=h;
  }
  __syncthreads();
  if (tid<16){
    float s1=0.f,s2=0.f;
    for(int bb=0;bb<64;bb++){ float v=a_s[bb*16+tid]; s1+=v; s2=fmaf(v,v,s2); }
    float m=s1*(1.f/64.f), v=s2*(1.f/64.f)-m*m;
    ms[tid]=m; rs[tid]=rsqrtf(v+1e-5f);
  }
  __syncthreads();
  {
    float h=a_s[b*16+hh];
    a_s[b*16+hh]=eluf(P.mdg[hh]*(h-ms[hh])*rs[hh]+P.mdbt[hh]);
  }
  __syncthreads();
  for (int q=tid;q<8192;q+=1024){
    int bb=q>>7, o=q&127;
    float r=0.f;
#pragma unroll
    for(int e=0;e<8;e++){
      float acc=P.mdb2[e*128+o];
#pragma unroll
      for(int k=0;k<16;k++) acc=fmaf(a_s[bb*16+k], P.mdw2[e*2048+k*128+o], acc);
      r=fmaf(om_s[bb*8+e],acc,r);
    }
    P.out[q]=r;
  }
}

extern "C" void kernel_launch(void* const* d_in, const int* in_sizes, int n_in,
                              void* d_out, int out_size)
{
  Params P;
  const float** f = (const float**)d_in;
  P.Local=f[0]; P.Remote=f[1];
  P.gWih0=f[2]; P.gWhh0=f[3]; P.gbih0=f[4]; P.gbhh0=f[5];
  P.gWih1=f[6]; P.gWhh1=f[7]; P.gbih1=f[8]; P.gbhh1=f[9];
  if (in_sizes[10] == 16384) {
    P.aew1=f[10]; P.aeb1=f[11]; P.aew2=f[12]; P.aeb2=f[13]; P.aeg=f[14]; P.aebt=f[15];
    P.mdw1=f[16]; P.mdb1=f[17]; P.mdw2=f[18]; P.mdb2=f[19]; P.mdg=f[20]; P.mdbt=f[21];
    P.mWih0=f[22]; P.mWhh0=f[23]; P.mbih0=f[24]; P.mbhh0=f[25];
    P.mWih1=f[26]; P.mWhh1=f[27]; P.mbih1=f[28]; P.mbhh1=f[29];
  } else {
    P.mWih0=f[10]; P.mWhh0=f[11]; P.mbih0=f[12]; P.mbhh0=f[13];
    P.mWih1=f[14]; P.mWhh1=f[15]; P.mbih1=f[16]; P.mbhh1=f[17];
    P.aew1=f[18]; P.aeb1=f[19]; P.aew2=f[20]; P.aeb2=f[21]; P.aeg=f[22]; P.aebt=f[23];
    P.mdw1=f[24]; P.mdb1=f[25]; P.mdw2=f[26]; P.mdb2=f[27]; P.mdg=f[28]; P.mdbt=f[29];
  }
  P.out=(float*)d_out;

  k1_gate_gemm<<<288,256>>>(P);
  k2_mix<<<128,256>>>(P);
  k3_z<<<64,256>>>(P);
  k4_mgru<<<32,32>>>(P);
  k5_dec<<<1,1024>>>(P);
}

// round 10
// speedup vs baseline: 1.3735x; 1.1769x over previous
#include <cuda_runtime.h>
#include <math.h>

// E=8 A=128 TGT=3 HID=16 OUT=128 B=64 W=128 F=132
struct Params {
  const float *Local, *Remote;
  const float *gWih0,*gWhh0,*gbih0,*gbhh0,*gWih1,*gWhh1,*gbih1,*gbhh1;
  const float *aew1,*aeb1,*aew2,*aeb2,*aeg,*aebt;
  const float *mdw1,*mdb1,*mdw2,*mdb2,*mdg,*mdbt;
  const float *mWih0,*mWhh0,*mbih0,*mbhh0,*mWih1,*mWhh1,*mbih1,*mbhh1;
  float* out;
};

__device__ __align__(16) float g_G[128*128*8];   // gate GRU hidden (pre-softmax) [seq][t][8]
__device__ __align__(16) float g_P[16384*128];   // expert-1 GEMM result
__device__ __align__(16) float g_H[16384*16];    // mixed hidden (pre-BN)
__device__             float g_stats[64];        // [call*32 + (sum16|sumsq16)]
__device__ __align__(16) float g_XW0[8192*48];   // mixer layer0 input projection (incl. bih0)
__device__ __align__(16) float g_HF[64*16];      // mixer final hidden

#define DEVFN __device__ __forceinline__
typedef unsigned long long u64;

DEVFN u64 pk2(float lo,float hi){u64 r;asm("mov.b64 %0,{%1,%2};":"=l"(r):"f"(lo),"f"(hi));return r;}
DEVFN float hadd2(u64 v){float lo,hi;asm("mov.b64 {%0,%1},%2;":"=f"(lo),"=f"(hi):"l"(v));return lo+hi;}
DEVFN u64 fma2(u64 a,u64 b,u64 c){u64 d;asm("fma.rn.f32x2 %0,%1,%2,%3;":"=l"(d):"l"(a),"l"(b),"l"(c));return d;}
DEVFN u64 add2(u64 a,u64 b){u64 d;asm("add.rn.f32x2 %0,%1,%2;":"=l"(d):"l"(a),"l"(b));return d;}
DEVFN float tanha(float x){float y;asm("tanh.approx.f32 %0,%1;":"=f"(y):"f"(x));return y;}
DEVFN float sigt(float x){ return fmaf(tanha(0.5f*x),0.5f,0.5f); }

DEVFN float eluf(float x){ return x>0.f ? x : (__expf(x)-1.f); }
DEVFN void softmax8(const float* gp, float* om){
  float g[8];
#pragma unroll
  for(int e=0;e<8;e++) g[e]=gp[e];
  float m=g[0];
#pragma unroll
  for(int e=1;e<8;e++) m=fmaxf(m,g[e]);
  float s=0.f;
#pragma unroll
  for(int e=0;e<8;e++){ om[e]=__expf(g[e]-m); s+=om[e]; }
  float inv=__fdividef(1.f,s);
#pragma unroll
  for(int e=0;e<8;e++) om[e]*=inv;
}

// ---------------- K1: gate GRU scan (blocks 0..31) + expert-1 GEMM (32..287) --
// Gate scan: 4 seqs/warp, 8 lanes/seq. x staged in SMEM (no in-loop LDG),
// smem h-broadcast, f32x2 packed dots, tanh.approx activations.
__global__ __launch_bounds__(256) void k1_gate_gemm(Params P)
{
  __shared__ __align__(16) float sb[2][2][4][8];     // [buf][h1|h2][seqInWarp][unit]
  __shared__ __align__(16) float sxg[4][129*3];      // staged gate inputs (+pad step)
  __shared__ float Xs[64][32];
  __shared__ float Ws[32][128];

  const int bid=blockIdx.x, tid=threadIdx.x;
  if (bid < 32) {
    if (bid==0 && tid>=32 && tid<96) g_stats[tid-32]=0.f;  // fresh stats each replay
    if (tid>=32) return;
    const int sw = tid>>3;                 // seq in warp 0..3
    const int s  = bid*4 + sw;             // seq 0..127 (0..63 Local, 64..127 Remote)
    const int j  = tid & 7;                // hidden unit

    // ---- stage x: 4 seqs x 128 steps x 3 feats into smem (pad t=128 w/ zeros)
#pragma unroll
    for (int ss=0; ss<4; ss++){
      const int sg=bid*4+ss, bb=sg&63;
      const float* Tb=((sg<64)?P.Local:P.Remote)+(size_t)bb*128*132+128;
      for (int tt=tid; tt<129; tt+=32){
        float a=0.f,b2=0.f,c=0.f;
        if (tt<128){ const float* p=Tb+(size_t)tt*132; a=p[0]; b2=p[1]; c=p[2]; }
        sxg[ss][tt*3+0]=a; sxg[ss][tt*3+1]=b2; sxg[ss][tt*3+2]=c;
      }
    }
    __syncwarp();

    // ih layer0 (scalar, input dim 3)
    float wxr0=P.gWih0[j*3+0],wxr1=P.gWih0[j*3+1],wxr2=P.gWih0[j*3+2];
    float wxz0=P.gWih0[(8+j)*3+0],wxz1=P.gWih0[(8+j)*3+1],wxz2=P.gWih0[(8+j)*3+2];
    float wxn0=P.gWih0[(16+j)*3+0],wxn1=P.gWih0[(16+j)*3+1],wxn2=P.gWih0[(16+j)*3+2];
    const float bxr=P.gbih0[j], bxz=P.gbih0[8+j], bxn=P.gbih0[16+j];
    // packed hh layer0
    u64 whrp[4],whzp[4],whnp[4];
#pragma unroll
    for(int k=0;k<4;k++){
      whrp[k]=pk2(P.gWhh0[j*8+2*k],P.gWhh0[j*8+2*k+1]);
      whzp[k]=pk2(P.gWhh0[(8+j)*8+2*k],P.gWhh0[(8+j)*8+2*k+1]);
      whnp[k]=pk2(P.gWhh0[(16+j)*8+2*k],P.gWhh0[(16+j)*8+2*k+1]);
    }
    const u64 bhrp=pk2(P.gbhh0[j],0.f), bhzp=pk2(P.gbhh0[8+j],0.f), bhnp=pk2(P.gbhh0[16+j],0.f);
    // packed ih layer1
    u64 uirp[4],uizp[4],uinp[4];
#pragma unroll
    for(int k=0;k<4;k++){
      uirp[k]=pk2(P.gWih1[j*8+2*k],P.gWih1[j*8+2*k+1]);
      uizp[k]=pk2(P.gWih1[(8+j)*8+2*k],P.gWih1[(8+j)*8+2*k+1]);
      uinp[k]=pk2(P.gWih1[(16+j)*8+2*k],P.gWih1[(16+j)*8+2*k+1]);
    }
    const u64 birp=pk2(P.gbih1[j],0.f), bizp=pk2(P.gbih1[8+j],0.f), binp=pk2(P.gbih1[16+j],0.f);
    // packed hh layer1
    u64 vhrp[4],vhzp[4],vhnp[4];
#pragma unroll
    for(int k=0;k<4;k++){
      vhrp[k]=pk2(P.gWhh1[j*8+2*k],P.gWhh1[j*8+2*k+1]);
      vhzp[k]=pk2(P.gWhh1[(8+j)*8+2*k],P.gWhh1[(8+j)*8+2*k+1]);
      vhnp[k]=pk2(P.gWhh1[(16+j)*8+2*k],P.gWhh1[(16+j)*8+2*k+1]);
    }
    const u64 cbrp=pk2(P.gbhh1[j],0.f), cbzp=pk2(P.gbhh1[8+j],0.f), cbnp=pk2(P.gbhh1[16+j],0.f);
    const float bhr_s=P.gbhh0[j], bhz_s=P.gbhh0[8+j], bhn_s=P.gbhh0[16+j];

    // prologue: layer1 at t=0 (h1_prev = 0 -> hh matvec reduces to bias)
    float h1,h2=0.f;
    {
      float x0=sxg[sw][0],x1=sxg[sw][1],x2=sxg[sw][2];
      float ir=fmaf(wxr2,x2,fmaf(wxr1,x1,fmaf(wxr0,x0,bxr)));
      float iz=fmaf(wxz2,x2,fmaf(wxz1,x1,fmaf(wxz0,x0,bxz)));
      float in_=fmaf(wxn2,x2,fmaf(wxn1,x1,fmaf(wxn0,x0,bxn)));
      float r=sigt(ir+bhr_s), z=sigt(iz+bhz_s), n=tanha(fmaf(r,bhn_s,in_));
      h1=fmaf(z,-n,n);
    }
    float* Gout = g_G + (size_t)s*128*8 + j;

    for (int t=0;t<128;t++){
      const int buf=t&1;
      sb[buf][0][sw][j]=h1; sb[buf][1][sw][j]=h2;
      __syncwarp();
      const ulonglong2* p1=(const ulonglong2*)&sb[buf][0][sw][0];
      const ulonglong2* p2=(const ulonglong2*)&sb[buf][1][sw][0];
      ulonglong2 v10=p1[0], v11=p1[1], v20=p2[0], v21=p2[1];
      u64 A1[4]={v10.x,v10.y,v11.x,v11.y};
      u64 A2[4]={v20.x,v20.y,v21.x,v21.y};
      // x(t+1) from smem (pad at t=127 -> zeros, result unused)
      const float* xq=&sxg[sw][(t+1)*3];
      float nx0=xq[0],nx1=xq[1],nx2=xq[2];
      // packed dots: layer2 (i2 from A1, q2 from A2) + layer1 hh (from A1)
      u64 i2r=birp,i2z=bizp,i2n=binp;
      u64 q2r=cbrp,q2z=cbzp,q2n=cbnp;
      u64 hr=bhrp, hz=bhzp, hn=bhnp;
#pragma unroll
      for(int k=0;k<4;k++){
        i2r=fma2(uirp[k],A1[k],i2r); i2z=fma2(uizp[k],A1[k],i2z); i2n=fma2(uinp[k],A1[k],i2n);
        q2r=fma2(vhrp[k],A2[k],q2r); q2z=fma2(vhzp[k],A2[k],q2z); q2n=fma2(vhnp[k],A2[k],q2n);
        hr =fma2(whrp[k],A1[k],hr ); hz =fma2(whzp[k],A1[k],hz ); hn =fma2(whnp[k],A1[k],hn );
      }
      float ir=fmaf(wxr2,nx2,fmaf(wxr1,nx1,fmaf(wxr0,nx0,bxr)));
      float iz=fmaf(wxz2,nx2,fmaf(wxz1,nx1,fmaf(wxz0,nx0,bxz)));
      float in_=fmaf(wxn2,nx2,fmaf(wxn1,nx1,fmaf(wxn0,nx0,bxn)));
      // activations layer2(t)
      float r2=sigt(hadd2(add2(i2r,q2r)));
      float z2=sigt(hadd2(add2(i2z,q2z)));
      float n2=tanha(fmaf(r2,hadd2(q2n),hadd2(i2n)));
      h2=fmaf(z2,h2-n2,n2);
      Gout[(size_t)t*8]=h2;
      // activations layer1(t+1)
      float r1=sigt(ir+hadd2(hr));
      float z1=sigt(iz+hadd2(hz));
      float n1=tanha(fmaf(r1,hadd2(hn),in_));
      h1=fmaf(z1,h1-n1,n1);
    }
    return;
  }
  // expert-1 GEMM: 64 rows x 128 cols per block
  {
    const int gb=bid-32, row0=gb*64;
    const int cg=tid&31, rg=tid>>5;
    float acc[8][4];
#pragma unroll
    for(int i=0;i<8;i++){acc[i][0]=0;acc[i][1]=0;acc[i][2]=0;acc[i][3]=0;}
    for (int kb=0;kb<128;kb+=32){
      for (int q=tid;q<512;q+=256){
        int r=q>>3, f4=q&7, row=row0+r;
        const float* xp=(row<8192)? (P.Local+(size_t)row*132) : (P.Remote+(size_t)(row-8192)*132);
        *(float4*)&Xs[r][f4*4] = *(const float4*)(xp+kb+f4*4);
      }
      for (int q=tid;q<1024;q+=256){
        int kk=q>>5, c=(q&31)*4, e=c>>4, h0=c&15;
        *(float4*)&Ws[kk][c] = *(const float4*)(P.aew1+(size_t)e*2048+(size_t)(kb+kk)*16+h0);
      }
      __syncthreads();
#pragma unroll
      for (int kk=0;kk<32;kk++){
        float4 w=*(float4*)&Ws[kk][cg*4];
#pragma unroll
        for(int i=0;i<8;i++){
          float x=Xs[rg*8+i][kk];
          acc[i][0]=fmaf(x,w.x,acc[i][0]); acc[i][1]=fmaf(x,w.y,acc[i][1]);
          acc[i][2]=fmaf(x,w.z,acc[i][2]); acc[i][3]=fmaf(x,w.w,acc[i][3]);
        }
      }
      __syncthreads();
    }
#pragma unroll
    for(int i=0;i<8;i++)
      *(float4*)&g_P[(size_t)(row0+rg*8+i)*128+cg*4] =
        make_float4(acc[i][0],acc[i][1],acc[i][2],acc[i][3]);
  }
}

// ---------------- K2: gated mix + BN stats ----------------------------------
__global__ __launch_bounds__(256) void k2_mix(Params P)
{
  const int tid=threadIdx.x;
  const int rowbase=blockIdx.x*128;
  const int call=rowbase>>13;
  const int hh=tid&15;
  float s1=0.f,s2=0.f;
  for (int pass=0;pass<8;pass++){
    const int row=rowbase+pass*16+(tid>>4);
    const int rr=row&8191, bb=rr>>7, w=rr&127;
    const float* gp=g_G+((size_t)(call*64+bb)*128+w)*8;
    float om[8]; softmax8(gp,om);
    const float* pp=g_P+(size_t)row*128+hh;
    float h=0.f;
#pragma unroll
    for(int e=0;e<8;e++) h=fmaf(om[e], pp[e*16]+P.aeb1[e*16+hh], h);
    g_H[(size_t)row*16+hh]=h;
    s1+=h; s2=fmaf(h,h,s2);
  }
  __shared__ float red[256];
  red[tid]=s1; __syncthreads();
  for(int off=128;off>=16;off>>=1){ if(tid<off) red[tid]+=red[tid+off]; __syncthreads(); }
  if(tid<16) atomicAdd(&g_stats[call*32+tid], red[tid]);
  __syncthreads();
  red[tid]=s2; __syncthreads();
  for(int off=128;off>=16;off>>=1){ if(tid<off) red[tid]+=red[tid+off]; __syncthreads(); }
  if(tid<16) atomicAdd(&g_stats[call*32+16+tid], red[tid]);
}

// ---------------- K3: BN+ELU+expert2; Z=ZL+ZR; mixer input proj -------------
__global__ __launch_bounds__(256) void k3_z(Params P)
{
  __shared__ float sw2[2048], sb2[128], sWm[768], sbm[48], sg[16], sbt[16];
  __shared__ float smean[32], srstd[32];
  __shared__ float zbuf[256*17];
  const int tid=threadIdx.x;
  for(int i=tid;i<2048;i+=256) sw2[i]=P.aew2[i];
  for(int i=tid;i<768;i+=256)  sWm[i]=P.mWih0[i];
  if(tid<128) sb2[tid]=P.aeb2[tid];
  if(tid<48)  sbm[tid]=P.mbih0[tid];
  if(tid<16){ sg[tid]=P.aeg[tid]; sbt[tid]=P.aebt[tid]; }
  if(tid<32){
    int c=tid>>4, hh=tid&15;
    float s1=g_stats[c*32+hh], s2=g_stats[c*32+16+hh];
    float m=s1*(1.f/8192.f), v=s2*(1.f/8192.f)-m*m;
    smean[tid]=m; srstd[tid]=rsqrtf(v+1e-5f);
  }
  __syncthreads();
  const int p=blockIdx.x*128+(tid&127);
  const int call=tid>>7;
  const int b=p>>7, w=p&127;
  const int row=call*8192+p;
  const float* gp=g_G+((size_t)(call*64+b)*128+w)*8;
  float om[8]; softmax8(gp,om);
  float a[16];
#pragma unroll
  for(int hh=0;hh<16;hh++){
    float h=g_H[(size_t)row*16+hh];
    a[hh]=eluf(sg[hh]*(h-smean[call*16+hh])*srstd[call*16+hh]+sbt[hh]);
  }
  float z[16];
#pragma unroll
  for(int o=0;o<16;o++) z[o]=0.f;
#pragma unroll
  for(int e=0;e<8;e++){
    float we=om[e];
#pragma unroll
    for(int o=0;o<16;o++){
      float acc=sb2[e*16+o];
#pragma unroll
      for(int hh=0;hh<16;hh++) acc=fmaf(a[hh], sw2[e*256+hh*16+o], acc);
      z[o]=fmaf(we,acc,z[o]);
    }
  }
#pragma unroll
  for(int o=0;o<16;o++) zbuf[tid*17+o]=z[o];
  __syncthreads();
  if(tid<128){
    const int pp=blockIdx.x*128+tid;
    float Z[16];
#pragma unroll
    for(int o=0;o<16;o++) Z[o]=zbuf[tid*17+o]+zbuf[(tid+128)*17+o];
    float* xo=g_XW0+(size_t)pp*48;
#pragma unroll
    for(int i=0;i<48;i++){
      float acc=sbm[i];
#pragma unroll
      for(int o=0;o<16;o++) acc=fmaf(sWm[i*16+o],Z[o],acc);
      xo[i]=acc;
    }
  }
}

// ---------------- K4: mixer GRU scan (1 seq/block, x staged in SMEM) --------
// All 32 lanes stage x; lanes 16-31 then redundantly mirror lanes 0-15
// (same j, same values -> benign) so full-mask __syncwarp stays valid.
__global__ __launch_bounds__(32,1) void k4_mgru(Params P)
{
  __shared__ __align__(16) float sx[129*48];        // staged inputs (+pad step)
  __shared__ __align__(16) float sb[2][2][16];      // [buf][h1|h2][unit]
  const int lane=threadIdx.x;
  const int s=blockIdx.x;
  const int j=lane&15;

  // stage the whole sequence's projected inputs (24KB) with float4 loads
  {
    const float4* src=(const float4*)(g_XW0+(size_t)s*6144);
    float4* dst=(float4*)sx;
    for(int q=lane;q<1536;q+=32) dst[q]=src[q];
    if(lane<12) dst[1536+lane]=make_float4(0.f,0.f,0.f,0.f);  // pad t=128
  }
  __syncwarp();

  u64 w0rp[8],w0zp[8],w0np[8];
#pragma unroll
  for(int k=0;k<8;k++){
    w0rp[k]=pk2(P.mWhh0[j*16+2*k],P.mWhh0[j*16+2*k+1]);
    w0zp[k]=pk2(P.mWhh0[(16+j)*16+2*k],P.mWhh0[(16+j)*16+2*k+1]);
    w0np[k]=pk2(P.mWhh0[(32+j)*16+2*k],P.mWhh0[(32+j)*16+2*k+1]);
  }
  const u64 b0rp=pk2(P.mbhh0[j],0.f), b0zp=pk2(P.mbhh0[16+j],0.f), b0np=pk2(P.mbhh0[32+j],0.f);
  const float b0r_s=P.mbhh0[j], b0z_s=P.mbhh0[16+j], b0n_s=P.mbhh0[32+j];
  u64 uirp[8],uizp[8],uinp[8];
#pragma unroll
  for(int k=0;k<8;k++){
    uirp[k]=pk2(P.mWih1[j*16+2*k],P.mWih1[j*16+2*k+1]);
    uizp[k]=pk2(P.mWih1[(16+j)*16+2*k],P.mWih1[(16+j)*16+2*k+1]);
    uinp[k]=pk2(P.mWih1[(32+j)*16+2*k],P.mWih1[(32+j)*16+2*k+1]);
  }
  const u64 birp=pk2(P.mbih1[j],0.f), bizp=pk2(P.mbih1[16+j],0.f), binp=pk2(P.mbih1[32+j],0.f);
  u64 vhrp[8],vhzp[8],vhnp[8];
#pragma unroll
  for(int k=0;k<8;k++){
    vhrp[k]=pk2(P.mWhh1[j*16+2*k],P.mWhh1[j*16+2*k+1]);
    vhzp[k]=pk2(P.mWhh1[(16+j)*16+2*k],P.mWhh1[(16+j)*16+2*k+1]);
    vhnp[k]=pk2(P.mWhh1[(32+j)*16+2*k],P.mWhh1[(32+j)*16+2*k+1]);
  }
  const u64 cbrp=pk2(P.mbhh1[j],0.f), cbzp=pk2(P.mbhh1[16+j],0.f), cbnp=pk2(P.mbhh1[32+j],0.f);

  // prologue: layer1 at t=0 (h1_prev = 0)
  float h1,h2=0.f;
  {
    float xr=sx[j], xz=sx[16+j], xn=sx[32+j];   // include bih0 already
    float r=sigt(xr+b0r_s), z=sigt(xz+b0z_s), n=tanha(fmaf(r,b0n_s,xn));
    h1=fmaf(z,-n,n);
  }
  for (int t=0;t<128;t++){
    const int buf=t&1;
    sb[buf][0][j]=h1; sb[buf][1][j]=h2;
    __syncwarp();
    const ulonglong2* p1=(const ulonglong2*)&sb[buf][0][0];
    const ulonglong2* p2=(const ulonglong2*)&sb[buf][1][0];
    ulonglong2 v10=p1[0], v11=p1[1], v12=p1[2], v13=p1[3];
    ulonglong2 v20=p2[0], v21=p2[1], v22=p2[2], v23=p2[3];
    u64 A1[8]={v10.x,v10.y,v11.x,v11.y,v12.x,v12.y,v13.x,v13.y};
    u64 A2[8]={v20.x,v20.y,v21.x,v21.y,v22.x,v22.y,v23.x,v23.y};
    const float* xq=&sx[(t+1)*48];
    float nxr=xq[j], nxz=xq[16+j], nxn=xq[32+j];
    u64 i2r=birp,i2z=bizp,i2n=binp;
    u64 q2r=cbrp,q2z=cbzp,q2n=cbnp;
    u64 hr=b0rp, hz=b0zp, hn=b0np;
#pragma unroll
    for(int k=0;k<8;k++){
      i2r=fma2(uirp[k],A1[k],i2r); i2z=fma2(uizp[k],A1[k],i2z); i2n=fma2(uinp[k],A1[k],i2n);
      q2r=fma2(vhrp[k],A2[k],q2r); q2z=fma2(vhzp[k],A2[k],q2z); q2n=fma2(vhnp[k],A2[k],q2n);
      hr =fma2(w0rp[k],A1[k],hr ); hz =fma2(w0zp[k],A1[k],hz ); hn =fma2(w0np[k],A1[k],hn );
    }
    // activations layer2(t)
    float r2=sigt(hadd2(add2(i2r,q2r)));
    float z2=sigt(hadd2(add2(i2z,q2z)));
    float n2=tanha(fmaf(r2,hadd2(q2n),hadd2(i2n)));
    h2=fmaf(z2,h2-n2,n2);
    // activations layer1(t+1)
    float r1=sigt(nxr+hadd2(hr));
    float z1=sigt(nxz+hadd2(hz));
    float n1=tanha(fmaf(r1,hadd2(hn),nxn));
    h1=fmaf(z1,h1-n1,n1);
  }
  g_HF[s*16+j]=h2;
}

// ---------------- K5: decoder expert (one block) ----------------------------
__global__ __launch_bounds__(1024) void k5_dec(Params P)
{
  __shared__ float om_s[64*8], x_s[64*17], a_s[64*16], ms[16], rs[16];
  const int tid=threadIdx.x;
  const int b=tid>>4, hh=tid&15;
  if (tid<64){
    const float* gp=g_G+((size_t)(64+tid)*128+127)*8;
    float om[8]; softmax8(gp,om);
#pragma unroll
    for(int e=0;e<8;e++) om_s[tid*8+e]=om[e];
    x_s[tid*17+16]=P.Remote[(size_t)tid*128*132+127*132+131];
  }
  x_s[b*17+hh]=g_HF[b*16+hh];
  __syncthreads();
  {
    float h=0.f;
#pragma unroll
    for(int e=0;e<8;e++){
      float acc=P.mdb1[e*16+hh];
#pragma unroll
      for(int i=0;i<17;i++) acc=fmaf(x_s[b*17+i], P.mdw1[e*272+i*16+hh], acc);
      h=fmaf(om_s[b*8+e],acc,h);
    }
    a_s[b*16+hh]=h;
  }
  __syncthreads();
  if (tid<16){
    float s1=0.f,s2=0.f;
    for(int bb=0;bb<64;bb++){ float v=a_s[bb*16+tid]; s1+=v; s2=fmaf(v,v,s2); }
    float m=s1*(1.f/64.f), v=s2*(1.f/64.f)-m*m;
    ms[tid]=m; rs[tid]=rsqrtf(v+1e-5f);
  }
  __syncthreads();
  {
    float h=a_s[b*16+hh];
    a_s[b*16+hh]=eluf(P.mdg[hh]*(h-ms[hh])*rs[hh]+P.mdbt[hh]);
  }
  __syncthreads();
  for (int q=tid;q<8192;q+=1024){
    int bb=q>>7, o=q&127;
    float r=0.f;
#pragma unroll
    for(int e=0;e<8;e++){
      float acc=P.mdb2[e*128+o];
#pragma unroll
      for(int k=0;k<16;k++) acc=fmaf(a_s[bb*16+k], P.mdw2[e*2048+k*128+o], acc);
      r=fmaf(om_s[bb*8+e],acc,r);
    }
    P.out[q]=r;
  }
}

extern "C" void kernel_launch(void* const* d_in, const int* in_sizes, int n_in,
                              void* d_out, int out_size)
{
  Params P;
  const float** f = (const float**)d_in;
  P.Local=f[0]; P.Remote=f[1];
  P.gWih0=f[2]; P.gWhh0=f[3]; P.gbih0=f[4]; P.gbhh0=f[5];
  P.gWih1=f[6]; P.gWhh1=f[7]; P.gbih1=f[8]; P.gbhh1=f[9];
  if (in_sizes[10] == 16384) {
    P.aew1=f[10]; P.aeb1=f[11]; P.aew2=f[12]; P.aeb2=f[13]; P.aeg=f[14]; P.aebt=f[15];
    P.mdw1=f[16]; P.mdb1=f[17]; P.mdw2=f[18]; P.mdb2=f[19]; P.mdg=f[20]; P.mdbt=f[21];
    P.mWih0=f[22]; P.mWhh0=f[23]; P.mbih0=f[24]; P.mbhh0=f[25];
    P.mWih1=f[26]; P.mWhh1=f[27]; P.mbih1=f[28]; P.mbhh1=f[29];
  } else {
    P.mWih0=f[10]; P.mWhh0=f[11]; P.mbih0=f[12]; P.mbhh0=f[13];
    P.mWih1=f[14]; P.mWhh1=f[15]; P.mbih1=f[16]; P.mbhh1=f[17];
    P.aew1=f[18]; P.aeb1=f[19]; P.aew2=f[20]; P.aeb2=f[21]; P.aeg=f[22]; P.aebt=f[23];
    P.mdw1=f[24]; P.mdb1=f[25]; P.mdw2=f[26]; P.mdb2=f[27]; P.mdg=f[28]; P.mdbt=f[29];
  }
  P.out=(float*)d_out;

  k1_gate_gemm<<<288,256>>>(P);
  k2_mix<<<128,256>>>(P);
  k3_z<<<64,256>>>(P);
  k4_mgru<<<64,32>>>(P);
  k5_dec<<<1,1024>>>(P);
}

// round 12
// speedup vs baseline: 1.5870x; 1.1554x over previous
#include <cuda_runtime.h>
#include <math.h>

// E=8 A=128 TGT=3 HID=16 OUT=128 B=64 W=128 F=132
struct Params {
  const float *Local, *Remote;
  const float *gWih0,*gWhh0,*gbih0,*gbhh0,*gWih1,*gWhh1,*gbih1,*gbhh1;
  const float *aew1,*aeb1,*aew2,*aeb2,*aeg,*aebt;
  const float *mdw1,*mdb1,*mdw2,*mdb2,*mdg,*mdbt;
  const float *mWih0,*mWhh0,*mbih0,*mbhh0,*mWih1,*mWhh1,*mbih1,*mbhh1;
  float* out;
};

__device__ __align__(16) float g_G[128*128*8];   // gate GRU hidden (pre-softmax) [seq][t][8]
__device__ __align__(16) float g_P[16384*128];   // expert-1 GEMM result
__device__ __align__(16) float g_H[16384*16];    // mixed hidden (pre-BN)
__device__             float g_stats[64];        // [call*32 + (sum16|sumsq16)]
__device__ __align__(16) float g_XW0[8192*48];   // mixer layer0 input projection (incl. bih0)
__device__ __align__(16) float g_HF[64*16];      // mixer final hidden
__device__ __align__(16) float g_C[64*128];      // decoder: om (x) a
__device__ __align__(16) float g_OMd[64*8];      // decoder gates

#define DEVFN __device__ __forceinline__
typedef unsigned long long u64;

DEVFN u64 pk2(float lo,float hi){u64 r;asm("mov.b64 %0,{%1,%2};":"=l"(r):"f"(lo),"f"(hi));return r;}
DEVFN float hadd2(u64 v){float lo,hi;asm("mov.b64 {%0,%1},%2;":"=f"(lo),"=f"(hi):"l"(v));return lo+hi;}
DEVFN u64 fma2(u64 a,u64 b,u64 c){u64 d;asm("fma.rn.f32x2 %0,%1,%2,%3;":"=l"(d):"l"(a),"l"(b),"l"(c));return d;}
DEVFN u64 add2(u64 a,u64 b){u64 d;asm("add.rn.f32x2 %0,%1,%2;":"=l"(d):"l"(a),"l"(b));return d;}
DEVFN float tanha(float x){float y;asm("tanh.approx.f32 %0,%1;":"=f"(y):"f"(x));return y;}
DEVFN float sigt(float x){ return fmaf(tanha(0.5f*x),0.5f,0.5f); }

DEVFN float eluf(float x){ return x>0.f ? x : (__expf(x)-1.f); }
DEVFN void softmax8(const float* gp, float* om){
  float g[8];
#pragma unroll
  for(int e=0;e<8;e++) g[e]=gp[e];
  float m=g[0];
#pragma unroll
  for(int e=1;e<8;e++) m=fmaxf(m,g[e]);
  float s=0.f;
#pragma unroll
  for(int e=0;e<8;e++){ om[e]=__expf(g[e]-m); s+=om[e]; }
  float inv=__fdividef(1.f,s);
#pragma unroll
  for(int e=0;e<8;e++) om[e]*=inv;
}

// ---------------- K1: gate GRU scan (blocks 0..31, 2 worker warps) + GEMM ----
// Gate blocks: warp0 = layer1 scan, warp1 = layer2 scan (one step behind),
// h1/h2 exchanged via double-buffered smem ring. ALL 256 threads stay alive
// and hit __syncthreads each step (no named barriers, no early exit).
__global__ __launch_bounds__(256) void k1_gate_gemm(Params P)
{
  __shared__ __align__(16) float h1r[2][4][8];
  __shared__ __align__(16) float h2r[2][4][8];
  __shared__ __align__(16) float sxg[4][129*3];      // staged gate inputs (+pad)
  __shared__ float Xs[64][32];
  __shared__ float Ws[32][128];

  const int bid=blockIdx.x, tid=threadIdx.x;
  if (bid < 32) {
    if (bid==0 && tid>=64 && tid<128) g_stats[tid-64]=0.f;  // fresh each replay
    const bool worker = tid<64;
    const int wp=tid>>5;                // 0 or 1 for workers
    const int lane=tid&31;
    const int sw=lane>>3, j=lane&7;
    const int s=bid*4+sw;

    // stage x with all 256 threads: 4 seqs x 129 steps x 3 feats (pad zeros)
#pragma unroll
    for (int ss=0; ss<4; ss++){
      const int sg=bid*4+ss, bb=sg&63;
      const float* Tb=((sg<64)?P.Local:P.Remote)+(size_t)bb*128*132+128;
      for (int tt=tid; tt<129; tt+=256){
        float a=0.f,b2=0.f,c=0.f;
        if (tt<128){ const float* p=Tb+(size_t)tt*132; a=p[0]; b2=p[1]; c=p[2]; }
        sxg[ss][tt*3+0]=a; sxg[ss][tt*3+1]=b2; sxg[ss][tt*3+2]=c;
      }
    }

    // per-warp weights (workers only)
    u64 Wr[4],Wz[4],Wn[4], Vr[4],Vz[4],Vn[4];
    u64 brp=0,bzp=0,bnp=0, crp=0,czp=0,cnp=0;
    float wxr0=0,wxr1=0,wxr2=0,wxz0=0,wxz1=0,wxz2=0,wxn0=0,wxn1=0,wxn2=0;
    float bxr=0,bxz=0,bxn=0, bhr_s=0,bhz_s=0,bhn_s=0;
#pragma unroll
    for(int k=0;k<4;k++){Wr[k]=0;Wz[k]=0;Wn[k]=0;Vr[k]=0;Vz[k]=0;Vn[k]=0;}
    if (worker && wp==0){
      wxr0=P.gWih0[j*3+0];wxr1=P.gWih0[j*3+1];wxr2=P.gWih0[j*3+2];
      wxz0=P.gWih0[(8+j)*3+0];wxz1=P.gWih0[(8+j)*3+1];wxz2=P.gWih0[(8+j)*3+2];
      wxn0=P.gWih0[(16+j)*3+0];wxn1=P.gWih0[(16+j)*3+1];wxn2=P.gWih0[(16+j)*3+2];
      bxr=P.gbih0[j]; bxz=P.gbih0[8+j]; bxn=P.gbih0[16+j];
#pragma unroll
      for(int k=0;k<4;k++){
        Wr[k]=pk2(P.gWhh0[j*8+2*k],P.gWhh0[j*8+2*k+1]);
        Wz[k]=pk2(P.gWhh0[(8+j)*8+2*k],P.gWhh0[(8+j)*8+2*k+1]);
        Wn[k]=pk2(P.gWhh0[(16+j)*8+2*k],P.gWhh0[(16+j)*8+2*k+1]);
      }
      brp=pk2(P.gbhh0[j],0.f); bzp=pk2(P.gbhh0[8+j],0.f); bnp=pk2(P.gbhh0[16+j],0.f);
      bhr_s=P.gbhh0[j]; bhz_s=P.gbhh0[8+j]; bhn_s=P.gbhh0[16+j];
    } else if (worker){
#pragma unroll
      for(int k=0;k<4;k++){
        Wr[k]=pk2(P.gWih1[j*8+2*k],P.gWih1[j*8+2*k+1]);
        Wz[k]=pk2(P.gWih1[(8+j)*8+2*k],P.gWih1[(8+j)*8+2*k+1]);
        Wn[k]=pk2(P.gWih1[(16+j)*8+2*k],P.gWih1[(16+j)*8+2*k+1]);
        Vr[k]=pk2(P.gWhh1[j*8+2*k],P.gWhh1[j*8+2*k+1]);
        Vz[k]=pk2(P.gWhh1[(8+j)*8+2*k],P.gWhh1[(8+j)*8+2*k+1]);
        Vn[k]=pk2(P.gWhh1[(16+j)*8+2*k],P.gWhh1[(16+j)*8+2*k+1]);
      }
      brp=pk2(P.gbih1[j],0.f); bzp=pk2(P.gbih1[8+j],0.f); bnp=pk2(P.gbih1[16+j],0.f);
      crp=pk2(P.gbhh1[j],0.f); czp=pk2(P.gbhh1[8+j],0.f); cnp=pk2(P.gbhh1[16+j],0.f);
    }
    __syncthreads();   // staging visible

    float h=0.f;
    if (worker && wp==0){   // prologue: h1(0), h1_prev=0 -> hh matvec = bias
      float x0=sxg[sw][0],x1=sxg[sw][1],x2=sxg[sw][2];
      float ir=fmaf(wxr2,x2,fmaf(wxr1,x1,fmaf(wxr0,x0,bxr)));
      float iz=fmaf(wxz2,x2,fmaf(wxz1,x1,fmaf(wxz0,x0,bxz)));
      float in_=fmaf(wxn2,x2,fmaf(wxn1,x1,fmaf(wxn0,x0,bxn)));
      float r=sigt(ir+bhr_s), z=sigt(iz+bhz_s), n=tanha(fmaf(r,bhn_s,in_));
      h=fmaf(z,-n,n);
    }
    float* Gout = g_G + (size_t)s*128*8 + j;

    for (int t=0;t<128;t++){
      const int buf=t&1;
      if (worker){ if (wp==0) h1r[buf][sw][j]=h; else h2r[buf][sw][j]=h; }
      __syncthreads();
      if (worker && wp==0){
        const ulonglong2* p1=(const ulonglong2*)&h1r[buf][sw][0];
        ulonglong2 v0=p1[0], v1=p1[1];
        u64 A1[4]={v0.x,v0.y,v1.x,v1.y};
        const float* xq=&sxg[sw][(t+1)*3];
        float nx0=xq[0],nx1=xq[1],nx2=xq[2];
        u64 hr=brp,hz=bzp,hn=bnp;
#pragma unroll
        for(int k=0;k<4;k++){ hr=fma2(Wr[k],A1[k],hr); hz=fma2(Wz[k],A1[k],hz); hn=fma2(Wn[k],A1[k],hn); }
        float ir=fmaf(wxr2,nx2,fmaf(wxr1,nx1,fmaf(wxr0,nx0,bxr)));
        float iz=fmaf(wxz2,nx2,fmaf(wxz1,nx1,fmaf(wxz0,nx0,bxz)));
        float in_=fmaf(wxn2,nx2,fmaf(wxn1,nx1,fmaf(wxn0,nx0,bxn)));
        float r1=sigt(ir+hadd2(hr));
        float z1=sigt(iz+hadd2(hz));
        float n1=tanha(fmaf(r1,hadd2(hn),in_));
        h=fmaf(z1,h-n1,n1);
      } else if (worker){
        const ulonglong2* p1=(const ulonglong2*)&h1r[buf][sw][0];
        const ulonglong2* p2=(const ulonglong2*)&h2r[buf][sw][0];
        ulonglong2 v10=p1[0], v11=p1[1], v20=p2[0], v21=p2[1];
        u64 A1[4]={v10.x,v10.y,v11.x,v11.y};
        u64 A2[4]={v20.x,v20.y,v21.x,v21.y};
        u64 i2r=brp,i2z=bzp,i2n=bnp, q2r=crp,q2z=czp,q2n=cnp;
#pragma unroll
        for(int k=0;k<4;k++){
          i2r=fma2(Wr[k],A1[k],i2r); i2z=fma2(Wz[k],A1[k],i2z); i2n=fma2(Wn[k],A1[k],i2n);
          q2r=fma2(Vr[k],A2[k],q2r); q2z=fma2(Vz[k],A2[k],q2z); q2n=fma2(Vn[k],A2[k],q2n);
        }
        float r2=sigt(hadd2(add2(i2r,q2r)));
        float z2=sigt(hadd2(add2(i2z,q2z)));
        float n2=tanha(fmaf(r2,hadd2(q2n),hadd2(i2n)));
        h=fmaf(z2,h-n2,n2);
        Gout[(size_t)t*8]=h;
      }
    }
    return;
  }
  // expert-1 GEMM: 64 rows x 128 cols per block
  {
    const int gb=bid-32, row0=gb*64;
    const int cg=tid&31, rg=tid>>5;
    float acc[8][4];
#pragma unroll
    for(int i=0;i<8;i++){acc[i][0]=0;acc[i][1]=0;acc[i][2]=0;acc[i][3]=0;}
    for (int kb=0;kb<128;kb+=32){
      for (int q=tid;q<512;q+=256){
        int r=q>>3, f4=q&7, row=row0+r;
        const float* xp=(row<8192)? (P.Local+(size_t)row*132) : (P.Remote+(size_t)(row-8192)*132);
        *(float4*)&Xs[r][f4*4] = *(const float4*)(xp+kb+f4*4);
      }
      for (int q=tid;q<1024;q+=256){
        int kk=q>>5, c=(q&31)*4, e=c>>4, h0=c&15;
        *(float4*)&Ws[kk][c] = *(const float4*)(P.aew1+(size_t)e*2048+(size_t)(kb+kk)*16+h0);
      }
      __syncthreads();
#pragma unroll
      for (int kk=0;kk<32;kk++){
        float4 w=*(float4*)&Ws[kk][cg*4];
#pragma unroll
        for(int i=0;i<8;i++){
          float x=Xs[rg*8+i][kk];
          acc[i][0]=fmaf(x,w.x,acc[i][0]); acc[i][1]=fmaf(x,w.y,acc[i][1]);
          acc[i][2]=fmaf(x,w.z,acc[i][2]); acc[i][3]=fmaf(x,w.w,acc[i][3]);
        }
      }
      __syncthreads();
    }
#pragma unroll
    for(int i=0;i<8;i++)
      *(float4*)&g_P[(size_t)(row0+rg*8+i)*128+cg*4] =
        make_float4(acc[i][0],acc[i][1],acc[i][2],acc[i][3]);
  }
}

// ---------------- K2: gated mix + BN stats ----------------------------------
__global__ __launch_bounds__(256) void k2_mix(Params P)
{
  const int tid=threadIdx.x;
  const int rowbase=blockIdx.x*128;
  const int call=rowbase>>13;
  const int hh=tid&15;
  float s1=0.f,s2=0.f;
  for (int pass=0;pass<8;pass++){
    const int row=rowbase+pass*16+(tid>>4);
    const int rr=row&8191, bb=rr>>7, w=rr&127;
    const float* gp=g_G+((size_t)(call*64+bb)*128+w)*8;
    float om[8]; softmax8(gp,om);
    const float* pp=g_P+(size_t)row*128+hh;
    float h=0.f;
#pragma unroll
    for(int e=0;e<8;e++) h=fmaf(om[e], pp[e*16]+P.aeb1[e*16+hh], h);
    g_H[(size_t)row*16+hh]=h;
    s1+=h; s2=fmaf(h,h,s2);
  }
  __shared__ float red[256];
  red[tid]=s1; __syncthreads();
  for(int off=128;off>=16;off>>=1){ if(tid<off) red[tid]+=red[tid+off]; __syncthreads(); }
  if(tid<16) atomicAdd(&g_stats[call*32+tid], red[tid]);
  __syncthreads();
  red[tid]=s2; __syncthreads();
  for(int off=128;off>=16;off>>=1){ if(tid<off) red[tid]+=red[tid+off]; __syncthreads(); }
  if(tid<16) atomicAdd(&g_stats[call*32+16+tid], red[tid]);
}

// ---------------- K3: BN+ELU+expert2; Z=ZL+ZR; mixer input proj -------------
__global__ __launch_bounds__(256) void k3_z(Params P)
{
  __shared__ float sw2[2048], sb2[128], sWm[768], sbm[48], sg[16], sbt[16];
  __shared__ float smean[32], srstd[32];
  __shared__ float zbuf[256*17];
  const int tid=threadIdx.x;
  for(int i=tid;i<2048;i+=256) sw2[i]=P.aew2[i];
  for(int i=tid;i<768;i+=256)  sWm[i]=P.mWih0[i];
  if(tid<128) sb2[tid]=P.aeb2[tid];
  if(tid<48)  sbm[tid]=P.mbih0[tid];
  if(tid<16){ sg[tid]=P.aeg[tid]; sbt[tid]=P.aebt[tid]; }
  if(tid<32){
    int c=tid>>4, hh=tid&15;
    float s1=g_stats[c*32+hh], s2=g_stats[c*32+16+hh];
    float m=s1*(1.f/8192.f), v=s2*(1.f/8192.f)-m*m;
    smean[tid]=m; srstd[tid]=rsqrtf(v+1e-5f);
  }
  __syncthreads();
  const int p=blockIdx.x*128+(tid&127);
  const int call=tid>>7;
  const int b=p>>7, w=p&127;
  const int row=call*8192+p;
  const float* gp=g_G+((size_t)(call*64+b)*128+w)*8;
  float om[8]; softmax8(gp,om);
  float a[16];
#pragma unroll
  for(int hh=0;hh<16;hh++){
    float h=g_H[(size_t)row*16+hh];
    a[hh]=eluf(sg[hh]*(h-smean[call*16+hh])*srstd[call*16+hh]+sbt[hh]);
  }
  float z[16];
#pragma unroll
  for(int o=0;o<16;o++) z[o]=0.f;
#pragma unroll
  for(int e=0;e<8;e++){
    float we=om[e];
#pragma unroll
    for(int o=0;o<16;o++){
      float acc=sb2[e*16+o];
#pragma unroll
      for(int hh=0;hh<16;hh++) acc=fmaf(a[hh], sw2[e*256+hh*16+o], acc);
      z[o]=fmaf(we,acc,z[o]);
    }
  }
#pragma unroll
  for(int o=0;o<16;o++) zbuf[tid*17+o]=z[o];
  __syncthreads();
  if(tid<128){
    const int pp=blockIdx.x*128+tid;
    float Z[16];
#pragma unroll
    for(int o=0;o<16;o++) Z[o]=zbuf[tid*17+o]+zbuf[(tid+128)*17+o];
    float* xo=g_XW0+(size_t)pp*48;
#pragma unroll
    for(int i=0;i<48;i++){
      float acc=sbm[i];
#pragma unroll
      for(int o=0;o<16;o++) acc=fmaf(sWm[i*16+o],Z[o],acc);
      xo[i]=acc;
    }
  }
}

// ---------------- K4: mixer GRU scan (1 seq/block, 2 warps pipelined) -------
// warp0 = layer1 scan (consumes staged x), warp1 = layer2 scan one step
// behind; h1 exchanged via double-buffered smem ring, 1 __syncthreads/step.
__global__ __launch_bounds__(64,1) void k4_mgru(Params P)
{
  __shared__ __align__(16) float sx[129*48];        // staged inputs (+pad step)
  __shared__ __align__(16) float h1r[2][16];
  __shared__ __align__(16) float h2r[2][16];
  const int tid=threadIdx.x;
  const int wp=tid>>5;
  const int j=tid&15;
  const int s=blockIdx.x;

  {
    const float4* src=(const float4*)(g_XW0+(size_t)s*6144);
    float4* dst=(float4*)sx;
    for(int q=tid;q<1536;q+=64) dst[q]=src[q];
    if(tid<12) dst[1536+tid]=make_float4(0.f,0.f,0.f,0.f);  // pad t=128
  }

  u64 Wr[8],Wz[8],Wn[8], Vr[8],Vz[8],Vn[8];
  u64 brp,bzp,bnp, crp=0,czp=0,cnp=0;
  float b0r_s=0,b0z_s=0,b0n_s=0;
  if (wp==0){
#pragma unroll
    for(int k=0;k<8;k++){
      Wr[k]=pk2(P.mWhh0[j*16+2*k],P.mWhh0[j*16+2*k+1]);
      Wz[k]=pk2(P.mWhh0[(16+j)*16+2*k],P.mWhh0[(16+j)*16+2*k+1]);
      Wn[k]=pk2(P.mWhh0[(32+j)*16+2*k],P.mWhh0[(32+j)*16+2*k+1]);
      Vr[k]=0;Vz[k]=0;Vn[k]=0;
    }
    brp=pk2(P.mbhh0[j],0.f); bzp=pk2(P.mbhh0[16+j],0.f); bnp=pk2(P.mbhh0[32+j],0.f);
    b0r_s=P.mbhh0[j]; b0z_s=P.mbhh0[16+j]; b0n_s=P.mbhh0[32+j];
  } else {
#pragma unroll
    for(int k=0;k<8;k++){
      Wr[k]=pk2(P.mWih1[j*16+2*k],P.mWih1[j*16+2*k+1]);
      Wz[k]=pk2(P.mWih1[(16+j)*16+2*k],P.mWih1[(16+j)*16+2*k+1]);
      Wn[k]=pk2(P.mWih1[(32+j)*16+2*k],P.mWih1[(32+j)*16+2*k+1]);
      Vr[k]=pk2(P.mWhh1[j*16+2*k],P.mWhh1[j*16+2*k+1]);
      Vz[k]=pk2(P.mWhh1[(16+j)*16+2*k],P.mWhh1[(16+j)*16+2*k+1]);
      Vn[k]=pk2(P.mWhh1[(32+j)*16+2*k],P.mWhh1[(32+j)*16+2*k+1]);
    }
    brp=pk2(P.mbih1[j],0.f); bzp=pk2(P.mbih1[16+j],0.f); bnp=pk2(P.mbih1[32+j],0.f);
    crp=pk2(P.mbhh1[j],0.f); czp=pk2(P.mbhh1[16+j],0.f); cnp=pk2(P.mbhh1[32+j],0.f);
  }
  __syncthreads();   // staging visible

  float h=0.f;
  if (wp==0){   // prologue: h1(0) with h1_prev = 0
    float xr=sx[j], xz=sx[16+j], xn=sx[32+j];
    float r=sigt(xr+b0r_s), z=sigt(xz+b0z_s), n=tanha(fmaf(r,b0n_s,xn));
    h=fmaf(z,-n,n);
  }

  for (int t=0;t<128;t++){
    const int buf=t&1;
    if (wp==0) h1r[buf][j]=h; else h2r[buf][j]=h;
    __syncthreads();
    if (wp==0){
      const ulonglong2* p1=(const ulonglong2*)&h1r[buf][0];
      ulonglong2 v0=p1[0], v1=p1[1], v2=p1[2], v3=p1[3];
      u64 A1[8]={v0.x,v0.y,v1.x,v1.y,v2.x,v2.y,v3.x,v3.y};
      const float* xq=&sx[(t+1)*48];
      float nxr=xq[j], nxz=xq[16+j], nxn=xq[32+j];
      u64 hr=brp,hz=bzp,hn=bnp;
#pragma unroll
      for(int k=0;k<8;k++){ hr=fma2(Wr[k],A1[k],hr); hz=fma2(Wz[k],A1[k],hz); hn=fma2(Wn[k],A1[k],hn); }
      float r1=sigt(nxr+hadd2(hr));
      float z1=sigt(nxz+hadd2(hz));
      float n1=tanha(fmaf(r1,hadd2(hn),nxn));
      h=fmaf(z1,h-n1,n1);
    } else {
      const ulonglong2* p1=(const ulonglong2*)&h1r[buf][0];
      const ulonglong2* p2=(const ulonglong2*)&h2r[buf][0];
      ulonglong2 v10=p1[0], v11=p1[1], v12=p1[2], v13=p1[3];
      ulonglong2 v20=p2[0], v21=p2[1], v22=p2[2], v23=p2[3];
      u64 A1[8]={v10.x,v10.y,v11.x,v11.y,v12.x,v12.y,v13.x,v13.y};
      u64 A2[8]={v20.x,v20.y,v21.x,v21.y,v22.x,v22.y,v23.x,v23.y};
      u64 i2r=brp,i2z=bzp,i2n=bnp, q2r=crp,q2z=czp,q2n=cnp;
#pragma unroll
      for(int k=0;k<8;k++){
        i2r=fma2(Wr[k],A1[k],i2r); i2z=fma2(Wz[k],A1[k],i2z); i2n=fma2(Wn[k],A1[k],i2n);
        q2r=fma2(Vr[k],A2[k],q2r); q2z=fma2(Vz[k],A2[k],q2z); q2n=fma2(Vn[k],A2[k],q2n);
      }
      float r2=sigt(hadd2(add2(i2r,q2r)));
      float z2=sigt(hadd2(add2(i2z,q2z)));
      float n2=tanha(fmaf(r2,hadd2(q2n),hadd2(i2n)));
      h=fmaf(z2,h-n2,n2);
    }
  }
  if (tid>=32 && tid<48) g_HF[s*16+j]=h;   // warp1 lanes 0..15 hold h2(127)
}

// ---------------- K5a: decoder hidden + BN + ELU; export C and om ----------
__global__ __launch_bounds__(1024) void k5a_dec(Params P)
{
  __shared__ float om_s[64*8], x_s[64*17], a_s[64*16], ms[16], rs[16];
  const int tid=threadIdx.x;
  const int b=tid>>4, hh=tid&15;
  if (tid<64){
    const float* gp=g_G+((size_t)(64+tid)*128+127)*8;
    float om[8]; softmax8(gp,om);
#pragma unroll
    for(int e=0;e<8;e++) om_s[tid*8+e]=om[e];
    x_s[tid*17+16]=P.Remote[(size_t)tid*128*132+127*132+131];
  }
  x_s[b*17+hh]=g_HF[b*16+hh];
  __syncthreads();
  {
    float h=0.f;
#pragma unroll
    for(int e=0;e<8;e++){
      float acc=P.mdb1[e*16+hh];
#pragma unroll
      for(int i=0;i<17;i++) acc=fmaf(x_s[b*17+i], P.mdw1[e*272+i*16+hh], acc);
      h=fmaf(om_s[b*8+e],acc,h);
    }
    a_s[b*16+hh]=h;
  }
  __syncthreads();
  if (tid<16){
    float s1=0.f,s2=0.f;
    for(int bb=0;bb<64;bb++){ float v=a_s[bb*16+tid]; s1+=v; s2=fmaf(v,v,s2); }
    float m=s1*(1.f/64.f), v=s2*(1.f/64.f)-m*m;
    ms[tid]=m; rs[tid]=rsqrtf(v+1e-5f);
  }
  __syncthreads();
  {
    float h=a_s[b*16+hh];
    a_s[b*16+hh]=eluf(P.mdg[hh]*(h-ms[hh])*rs[hh]+P.mdbt[hh]);
  }
  __syncthreads();
  // export C[b][e*16+k] = om[b][e]*a[b][k]  and om
  for (int q=tid;q<8192;q+=1024){
    int bb=q>>7, m=q&127, e=m>>4, k=m&15;
    g_C[q]=om_s[bb*8+e]*a_s[bb*16+k];
  }
  if (tid<512) g_OMd[tid]=om_s[tid];
}

// ---------------- K5b: decoder output GEMM out = C @ mdw2_v + om.b2 --------
__global__ __launch_bounds__(256) void k5b_dec(Params P)
{
  __shared__ float sC[2][128], sOM[2][8];
  const int tid=threadIdx.x;
  const int b0=blockIdx.x*2;
  sC[tid>>7][tid&127]=g_C[(size_t)b0*128+tid];
  if (tid<16) sOM[tid>>3][tid&7]=g_OMd[b0*8+tid];
  __syncthreads();
  const int lb=tid>>7, o=tid&127;
  float acc=0.f;
#pragma unroll 4
  for (int m=0;m<128;m++) acc=fmaf(sC[lb][m], P.mdw2[(size_t)m*128+o], acc);
#pragma unroll
  for (int e=0;e<8;e++) acc=fmaf(sOM[lb][e], P.mdb2[e*128+o], acc);
  P.out[(size_t)(b0+lb)*128+o]=acc;
}

extern "C" void kernel_launch(void* const* d_in, const int* in_sizes, int n_in,
                              void* d_out, int out_size)
{
  Params P;
  const float** f = (const float**)d_in;
  P.Local=f[0]; P.Remote=f[1];
  P.gWih0=f[2]; P.gWhh0=f[3]; P.gbih0=f[4]; P.gbhh0=f[5];
  P.gWih1=f[6]; P.gWhh1=f[7]; P.gbih1=f[8]; P.gbhh1=f[9];
  if (in_sizes[10] == 16384) {
    P.aew1=f[10]; P.aeb1=f[11]; P.aew2=f[12]; P.aeb2=f[13]; P.aeg=f[14]; P.aebt=f[15];
    P.mdw1=f[16]; P.mdb1=f[17]; P.mdw2=f[18]; P.mdb2=f[19]; P.mdg=f[20]; P.mdbt=f[21];
    P.mWih0=f[22]; P.mWhh0=f[23]; P.mbih0=f[24]; P.mbhh0=f[25];
    P.mWih1=f[26]; P.mWhh1=f[27]; P.mbih1=f[28]; P.mbhh1=f[29];
  } else {
    P.mWih0=f[10]; P.mWhh0=f[11]; P.mbih0=f[12]; P.mbhh0=f[13];
    P.mWih1=f[14]; P.mWhh1=f[15]; P.mbih1=f[16]; P.mbhh1=f[17];
    P.aew1=f[18]; P.aeb1=f[19]; P.aew2=f[20]; P.aeb2=f[21]; P.aeg=f[22]; P.aebt=f[23];
    P.mdw1=f[24]; P.mdb1=f[25]; P.mdw2=f[26]; P.mdb2=f[27]; P.mdg=f[28]; P.mdbt=f[29];
  }
  P.out=(float*)d_out;

  k1_gate_gemm<<<288,256>>>(P);
  k2_mix<<<128,256>>>(P);
  k3_z<<<64,256>>>(P);
  k4_mgru<<<64,64>>>(P);
  k5a_dec<<<1,1024>>>(P);
  k5b_dec<<<32,256>>>(P);
}